// round 3
// baseline (speedup 1.0000x reference)
#include <cuda_runtime.h>

#define N_NODES  50000
#define N_EDGES  50000
#define N_GRAPHS 1024
#define N_INC    400000
#define MAXDIM   512

// ---------------- scratch (device globals; referenced ONLY from device code) ----
__device__ float g_xl[N_NODES * MAXDIM];   // GEMM output; reused as node-accumulator
__device__ float g_ef[N_NODES * MAXDIM];   // hyperedge features
__device__ float g_hA[N_NODES * 256];      // layer1 / layer3 activations
__device__ float g_hB[N_NODES * MAXDIM];   // layer2 activations
__device__ float g_dinv[N_NODES];          // inverse node degree
__device__ float g_binv[N_EDGES];          // inverse hyperedge degree
__device__ float g_cnt[N_GRAPHS];          // nodes per graph
__device__ float g_pool[N_GRAPHS * 256];   // pooled features

// device-side buffer selector (avoids any host symbol-address API)
__device__ __forceinline__ float* bufp(int s) {
    switch (s) {
        case 0: return g_xl;
        case 1: return g_ef;
        case 2: return g_hA;
        case 3: return g_hB;
        case 4: return g_dinv;
        case 5: return g_binv;
        case 6: return g_cnt;
        default: return g_pool;
    }
}

// ---------------- utility ----------------
__global__ void fillzero(int sel, int n) {
    float* p = bufp(sel);
    for (int i = blockIdx.x * blockDim.x + threadIdx.x; i < n;
         i += gridDim.x * blockDim.x)
        p[i] = 0.f;
}

// ---------------- degree / count ----------------
__global__ void deg_k(const int* __restrict__ nidx,
                      const int* __restrict__ eidx) {
    int i = blockIdx.x * blockDim.x + threadIdx.x;
    if (i < N_INC) {
        atomicAdd(&g_dinv[nidx[i]], 1.f);
        atomicAdd(&g_binv[eidx[i]], 1.f);
    }
}

__global__ void cnt_k(const int* __restrict__ batch) {
    int i = blockIdx.x * blockDim.x + threadIdx.x;
    if (i < N_NODES) atomicAdd(&g_cnt[batch[i]], 1.f);
}

__global__ void inv_k() {
    int i = blockIdx.x * blockDim.x + threadIdx.x;
    if (i < N_NODES) {
        float d = g_dinv[i];
        g_dinv[i] = d > 0.f ? 1.f / d : 0.f;
        float b = g_binv[i];
        g_binv[i] = b > 0.f ? 1.f / b : 0.f;
    }
}

// ---------------- SGEMM: g_xl[N,M] = A[N,K] @ W[K,M] (row-major) ----------------
// 128x64 tile, BK=16, 256 threads, 8x4 register tile.
__global__ void __launch_bounds__(256) gemm_k(
    const float* __restrict__ Aext, int Asel,
    const float* __restrict__ W, int N, int K, int M) {
    const float* A = (Asel >= 0) ? bufp(Asel) : Aext;
    float* C = g_xl;

    __shared__ float As[16][128];
    __shared__ float Ws[16][64];

    const int tid = threadIdx.x;
    const int tx = tid & 15;        // 0..15 -> 4 cols each
    const int ty = tid >> 4;        // 0..15 -> 8 rows each
    const int rowBase = blockIdx.x * 128;
    const int colBase = blockIdx.y * 64;

    const int aRow = tid >> 1;          // 0..127
    const int aK   = (tid & 1) * 8;     // 0 or 8
    const int wK   = tid >> 4;          // 0..15
    const int wM   = (tid & 15) * 4;    // 0..60

    float acc[8][4];
#pragma unroll
    for (int i = 0; i < 8; i++)
#pragma unroll
        for (int j = 0; j < 4; j++) acc[i][j] = 0.f;

    for (int k0 = 0; k0 < K; k0 += 16) {
        const int gr = rowBase + aRow;
        float4 a0 = make_float4(0.f, 0.f, 0.f, 0.f), a1 = a0;
        if (gr < N) {
            const float4* ap = (const float4*)(A + (size_t)gr * K + k0 + aK);
            a0 = ap[0];
            a1 = ap[1];
        }
        As[aK + 0][aRow] = a0.x; As[aK + 1][aRow] = a0.y;
        As[aK + 2][aRow] = a0.z; As[aK + 3][aRow] = a0.w;
        As[aK + 4][aRow] = a1.x; As[aK + 5][aRow] = a1.y;
        As[aK + 6][aRow] = a1.z; As[aK + 7][aRow] = a1.w;

        *(float4*)&Ws[wK][wM] =
            *(const float4*)(W + (size_t)(k0 + wK) * M + colBase + wM);
        __syncthreads();

#pragma unroll
        for (int k = 0; k < 16; k++) {
            float4 wv  = *(const float4*)&Ws[k][tx * 4];
            float4 av0 = *(const float4*)&As[k][ty * 8];
            float4 av1 = *(const float4*)&As[k][ty * 8 + 4];
            float ar[8] = {av0.x, av0.y, av0.z, av0.w, av1.x, av1.y, av1.z, av1.w};
            float wr[4] = {wv.x, wv.y, wv.z, wv.w};
#pragma unroll
            for (int i = 0; i < 8; i++)
#pragma unroll
                for (int j = 0; j < 4; j++)
                    acc[i][j] = fmaf(ar[i], wr[j], acc[i][j]);
        }
        __syncthreads();
    }

#pragma unroll
    for (int i = 0; i < 8; i++) {
        int row = rowBase + ty * 8 + i;
        if (row < N) {
            float4 v = make_float4(acc[i][0], acc[i][1], acc[i][2], acc[i][3]);
            *(float4*)(C + (size_t)row * M + colBase + tx * 4) = v;
        }
    }
}

// ---------------- scatter: node -> hyperedge (g_ef[e] += g_xl[n]) --------------
__global__ void scat_n2e(const int* __restrict__ nidx,
                         const int* __restrict__ eidx, int dim) {
    const int f  = (blockIdx.y << 8) | threadIdx.x;
    const int i0 = blockIdx.x << 2;
#pragma unroll
    for (int t = 0; t < 4; t++) {
        const int i = i0 + t;
        const int n = nidx[i];
        const int e = eidx[i];
        atomicAdd(&g_ef[e * dim + f], g_xl[n * dim + f]);
    }
}

// ---------------- scatter: hyperedge -> node (g_xl[n] += B^-1[e]*g_ef[e]) ------
__global__ void scat_e2n(const int* __restrict__ nidx,
                         const int* __restrict__ eidx, int dim) {
    const int f  = (blockIdx.y << 8) | threadIdx.x;
    const int i0 = blockIdx.x << 2;
#pragma unroll
    for (int t = 0; t < 4; t++) {
        const int i = i0 + t;
        const int n = nidx[i];
        const int e = eidx[i];
        atomicAdd(&g_xl[n * dim + f], g_binv[e] * g_ef[e * dim + f]);
    }
}

// ---------------- epilogue: h = relu(D^-1 * g_xl + b) ----------------
__global__ void act_k(const float* __restrict__ bias, int outSel,
                      int total, int shift, int mask) {
    float* h = bufp(outSel);
    int i = blockIdx.x * 256 + threadIdx.x;
    if (i >= total) return;
    int row = i >> shift;
    int col = i & mask;
    h[i] = fmaxf(fmaf(g_dinv[row], g_xl[i], bias[col]), 0.f);
}

// ---------------- global mean pool (sum part; reads g_hA) ----------------
__global__ void pool_k(const int* __restrict__ batch) {
    int i = blockIdx.x * 256 + threadIdx.x;
    if (i >= N_NODES * 256) return;
    int row = i >> 8;
    int col = i & 255;
    atomicAdd(&g_pool[(batch[row] << 8) + col], g_hA[i]);
}

// ---------------- final MLP (mean, 256->128 relu, 128->1) ----------------
__global__ void __launch_bounds__(256) mlp_k(
    const float* __restrict__ Wl1, const float* __restrict__ bl1,
    const float* __restrict__ Wl2, const float* __restrict__ bl2,
    float* __restrict__ out) {
    __shared__ float sp[256];
    __shared__ float red[128];
    const int g = blockIdx.x;
    const int t = threadIdx.x;

    const float ic = 1.f / fmaxf(g_cnt[g], 1.f);
    sp[t] = g_pool[(g << 8) + t] * ic;
    __syncthreads();

    if (t < 128) {
        float a = bl1[t];
#pragma unroll 8
        for (int k = 0; k < 256; k++) a = fmaf(sp[k], Wl1[k * 128 + t], a);
        a = fmaxf(a, 0.f);
        red[t] = a * Wl2[t];
    }
    __syncthreads();
    for (int s = 64; s > 0; s >>= 1) {
        if (t < s) red[t] += red[t + s];
        __syncthreads();
    }
    if (t == 0) out[g] = red[0] + bl2[0];
}

// ---------------- host-side layer driver ----------------
static void run_layer(const float* inExt, int inSel, int K, int M,
                      const float* W, const float* b,
                      const int* nidx, const int* eidx,
                      int outSel) {
    dim3 gg((N_NODES + 127) / 128, M / 64);
    gemm_k<<<gg, 256>>>(inExt, inSel, W, N_NODES, K, M);

    const int cnt = N_NODES * M;
    fillzero<<<8192, 256>>>(1, cnt);                       // zero g_ef

    dim3 sg(N_INC / 4, M / 256);
    scat_n2e<<<sg, 256>>>(nidx, eidx, M);

    fillzero<<<8192, 256>>>(0, cnt);                       // zero g_xl
    scat_e2n<<<sg, 256>>>(nidx, eidx, M);

    const int shift = (M == 256) ? 8 : 9;
    act_k<<<(cnt + 255) / 256, 256>>>(b, outSel, cnt, shift, M - 1);
}

extern "C" void kernel_launch(void* const* d_in, const int* in_sizes, int n_in,
                              void* d_out, int out_size) {
    const float* x     = (const float*)d_in[0];
    const int*   hei   = (const int*)d_in[1];     // int32! (JAX x64-disabled demotes int64)
    const int*   batch = (const int*)d_in[2];
    const float *W1  = (const float*)d_in[3],  *b1  = (const float*)d_in[4];
    const float *W2  = (const float*)d_in[5],  *b2  = (const float*)d_in[6];
    const float *W3  = (const float*)d_in[7],  *b3  = (const float*)d_in[8];
    const float *Wl1 = (const float*)d_in[9],  *bl1 = (const float*)d_in[10];
    const float *Wl2 = (const float*)d_in[11], *bl2 = (const float*)d_in[12];
    const int* nidx = hei;
    const int* eidx = hei + N_INC;
    float* out = (float*)d_out;

    // degrees / counts (once per launch)
    fillzero<<<256, 256>>>(4, N_NODES);          // g_dinv
    fillzero<<<256, 256>>>(5, N_EDGES);          // g_binv
    fillzero<<<8,   256>>>(6, N_GRAPHS);         // g_cnt
    fillzero<<<1024, 256>>>(7, N_GRAPHS * 256);  // g_pool
    deg_k<<<(N_INC + 255) / 256, 256>>>(nidx, eidx);
    cnt_k<<<(N_NODES + 255) / 256, 256>>>(batch);
    inv_k<<<(N_NODES + 255) / 256, 256>>>();

    // three hypergraph conv layers
    run_layer(x,       -1, 128, 256, W1, b1, nidx, eidx, 2);  // -> g_hA
    run_layer(nullptr,  2, 256, 512, W2, b2, nidx, eidx, 3);  // g_hA -> g_hB
    run_layer(nullptr,  3, 512, 256, W3, b3, nidx, eidx, 2);  // g_hB -> g_hA

    // pool + MLP head
    pool_k<<<(N_NODES * 256 + 255) / 256, 256>>>(batch);
    mlp_k<<<N_GRAPHS, 256>>>(Wl1, bl1, Wl2, bl2, out);
}

// round 4
// speedup vs baseline: 1.4550x; 1.4550x over previous
#include <cuda_runtime.h>

#define N_NODES  50000
#define N_EDGES  50000
#define N_GRAPHS 1024
#define N_INC    400000

// ---------------- scratch (device globals; device-side refs only) ----------------
__device__ float g_acc[N_NODES * 256];     // scatter node-accumulator / gemm3 out
__device__ float g_ef [N_NODES * 256];     // hyperedge accumulator
__device__ float g_hA [N_NODES * 256];     // layer1 out / final activations
__device__ float g_hB [N_NODES * 512];     // layer2 out (also e2n target for L3)
__device__ float g_dinv[N_NODES];
__device__ float g_binv[N_EDGES];
__device__ float g_cnt [N_GRAPHS];
__device__ float g_pool[N_GRAPHS * 256];

__device__ __forceinline__ float* bufp(int s) {
    switch (s) {
        case 0: return g_acc;
        case 1: return g_ef;
        case 2: return g_hA;
        case 3: return g_hB;
        case 4: return g_dinv;
        case 5: return g_binv;
        case 6: return g_cnt;
        default: return g_pool;
    }
}

// vector fp32 reduction (sm_90+): 4 lanes in one RED
__device__ __forceinline__ void red4(float* p, float4 v) {
    asm volatile("red.global.v4.f32.add [%0], {%1,%2,%3,%4};"
                 :: "l"(p), "f"(v.x), "f"(v.y), "f"(v.z), "f"(v.w) : "memory");
}

// ---------------- fills ----------------
__global__ void fill_init() {  // zero dinv, binv, cnt, pool
    int i = blockIdx.x * 256 + threadIdx.x;           // grid covers 262144
    if (i < N_NODES)       g_dinv[i] = 0.f;
    if (i < N_EDGES)       g_binv[i] = 0.f;
    if (i < N_GRAPHS)      g_cnt[i]  = 0.f;
    if (i < N_GRAPHS * 256) g_pool[i] = 0.f;
}

__global__ void fillzero(int sel, int n4) {           // n4 = float4 count
    float4* p = (float4*)bufp(sel);
    float4 z = make_float4(0.f, 0.f, 0.f, 0.f);
    for (int i = blockIdx.x * blockDim.x + threadIdx.x; i < n4;
         i += gridDim.x * blockDim.x)
        p[i] = z;
}

// ---------------- degree / count ----------------
__global__ void deg_k(const int* __restrict__ nidx, const int* __restrict__ eidx) {
    int i = blockIdx.x * blockDim.x + threadIdx.x;
    if (i < N_INC) {
        atomicAdd(&g_dinv[nidx[i]], 1.f);
        atomicAdd(&g_binv[eidx[i]], 1.f);
    }
}
__global__ void cnt_k(const int* __restrict__ batch) {
    int i = blockIdx.x * blockDim.x + threadIdx.x;
    if (i < N_NODES) atomicAdd(&g_cnt[batch[i]], 1.f);
}
__global__ void inv_k() {
    int i = blockIdx.x * blockDim.x + threadIdx.x;
    if (i < N_NODES) {
        float d = g_dinv[i]; g_dinv[i] = d > 0.f ? 1.f / d : 0.f;
        float b = g_binv[i]; g_binv[i] = b > 0.f ? 1.f / b : 0.f;
    }
}

// ---------------- scatters (vector atomics) ----------------
// q = dim/4 float4 lanes per incidence; 256 threads handle (256>>log2q) incidences
__global__ void scat_n2e(const float* __restrict__ inExt, int inSel,
                         const int* __restrict__ nidx, const int* __restrict__ eidx,
                         int log2q) {
    const float* in = (inSel >= 0) ? bufp(inSel) : inExt;
    const int t  = threadIdx.x;
    const int q  = 1 << log2q;
    const int j  = t & (q - 1);
    const int i  = blockIdx.x * (256 >> log2q) + (t >> log2q);
    const int dim = q << 2;
    const int n = nidx[i], e = eidx[i];
    float4 v = *(const float4*)(in + (size_t)n * dim + 4 * j);
    red4(&g_ef[(size_t)e * dim + 4 * j], v);
}

__global__ void scat_e2n(int outSel,
                         const int* __restrict__ nidx, const int* __restrict__ eidx,
                         int log2q) {
    float* outb = bufp(outSel);
    const int t  = threadIdx.x;
    const int q  = 1 << log2q;
    const int j  = t & (q - 1);
    const int i  = blockIdx.x * (256 >> log2q) + (t >> log2q);
    const int dim = q << 2;
    const int n = nidx[i], e = eidx[i];
    const float bw = g_binv[e];
    float4 v = *(const float4*)(g_ef + (size_t)e * dim + 4 * j);
    v.x *= bw; v.y *= bw; v.z *= bw; v.w *= bw;
    red4(&outb[(size_t)n * dim + 4 * j], v);
}

// ---------------- SGEMM 128x128 tile, BK=8, 8x8 microtile -----------------------
// C[N,M] = (scaleA? dinv⊙A : A)[N,K] @ W[K,M]; epi: 0 none, 1 bias+relu
__global__ void __launch_bounds__(256) gemm_k(
    const float* __restrict__ Aext, int Asel, const float* __restrict__ W,
    const float* __restrict__ bias, int outSel,
    int N, int K, int M, int scaleA, int doEpi) {
    const float* A = (Asel >= 0) ? bufp(Asel) : Aext;
    float* C = bufp(outSel);

    __shared__ float As[8][132];
    __shared__ float Bs[8][128];

    const int tid = threadIdx.x;
    const int tx = tid & 15;            // col group (8 cols)
    const int ty = tid >> 4;            // row group (8 rows)
    const int rowBase = blockIdx.x * 128;
    const int colBase = blockIdx.y * 128;

    const int aRow = tid >> 1;          // 0..127
    const int aOff = (tid & 1) * 4;     // k offset 0/4
    const int bRow = tid >> 5;          // 0..7
    const int bCol = (tid & 31) * 4;    // 0..124

    const int row = rowBase + aRow;
    float ds = 1.f;
    if (scaleA && row < N) ds = g_dinv[row];

    float acc[8][8];
#pragma unroll
    for (int i = 0; i < 8; i++)
#pragma unroll
        for (int j = 0; j < 8; j++) acc[i][j] = 0.f;

    const float4 z4 = make_float4(0.f, 0.f, 0.f, 0.f);
    float4 av = (row < N) ? *(const float4*)(A + (size_t)row * K + aOff) : z4;
    float4 bv = *(const float4*)(W + (size_t)bRow * M + colBase + bCol);

    for (int k0 = 0; k0 < K; k0 += 8) {
        av.x *= ds; av.y *= ds; av.z *= ds; av.w *= ds;
        As[aOff + 0][aRow] = av.x; As[aOff + 1][aRow] = av.y;
        As[aOff + 2][aRow] = av.z; As[aOff + 3][aRow] = av.w;
        *(float4*)&Bs[bRow][bCol] = bv;
        __syncthreads();

        if (k0 + 8 < K) {   // prefetch next tile while computing
            av = (row < N) ? *(const float4*)(A + (size_t)row * K + k0 + 8 + aOff) : z4;
            bv = *(const float4*)(W + (size_t)(k0 + 8 + bRow) * M + colBase + bCol);
        }

#pragma unroll
        for (int k = 0; k < 8; k++) {
            float ar[8], br[8];
            *(float4*)&ar[0] = *(const float4*)&As[k][ty * 8];
            *(float4*)&ar[4] = *(const float4*)&As[k][ty * 8 + 4];
            *(float4*)&br[0] = *(const float4*)&Bs[k][tx * 8];
            *(float4*)&br[4] = *(const float4*)&Bs[k][tx * 8 + 4];
#pragma unroll
            for (int i = 0; i < 8; i++)
#pragma unroll
                for (int j = 0; j < 8; j++)
                    acc[i][j] = fmaf(ar[i], br[j], acc[i][j]);
        }
        __syncthreads();
    }

    float bl[8];
    if (doEpi) {
#pragma unroll
        for (int j = 0; j < 8; j++) bl[j] = bias[colBase + tx * 8 + j];
    }
#pragma unroll
    for (int i = 0; i < 8; i++) {
        int r = rowBase + ty * 8 + i;
        if (r < N) {
            float v[8];
#pragma unroll
            for (int j = 0; j < 8; j++) {
                float c = acc[i][j];
                if (doEpi) c = fmaxf(c + bl[j], 0.f);
                v[j] = c;
            }
            float* cp = C + (size_t)r * M + colBase + tx * 8;
            *(float4*)cp       = *(float4*)&v[0];
            *(float4*)(cp + 4) = *(float4*)&v[4];
        }
    }
}

// ---------------- layer-3 epilogue: hA = relu(dinv * hB + b) --------------------
__global__ void act3_k(const float* __restrict__ bias) {
    int i = blockIdx.x * 256 + threadIdx.x;
    if (i >= N_NODES * 256) return;
    g_hA[i] = fmaxf(fmaf(g_dinv[i >> 8], g_hB[i], bias[i & 255]), 0.f);
}

// ---------------- global mean pool (sum; vectorized atomics) --------------------
__global__ void pool_k(const int* __restrict__ batch) {
    int i = blockIdx.x * 256 + threadIdx.x;
    if (i >= N_NODES * 64) return;
    int row = i >> 6;
    int j   = i & 63;
    float4 v = *(const float4*)(g_hA + (size_t)row * 256 + 4 * j);
    red4(&g_pool[(batch[row] << 8) + 4 * j], v);
}

// ---------------- final MLP ----------------
__global__ void __launch_bounds__(256) mlp_k(
    const float* __restrict__ Wl1, const float* __restrict__ bl1,
    const float* __restrict__ Wl2, const float* __restrict__ bl2,
    float* __restrict__ out) {
    __shared__ float sp[256];
    __shared__ float red[128];
    const int g = blockIdx.x;
    const int t = threadIdx.x;

    const float ic = 1.f / fmaxf(g_cnt[g], 1.f);
    sp[t] = g_pool[(g << 8) + t] * ic;
    __syncthreads();

    if (t < 128) {
        float a = bl1[t];
#pragma unroll 8
        for (int k = 0; k < 256; k++) a = fmaf(sp[k], Wl1[k * 128 + t], a);
        red[t] = fmaxf(a, 0.f) * Wl2[t];
    }
    __syncthreads();
    for (int s = 64; s > 0; s >>= 1) {
        if (t < s) red[t] += red[t + s];
        __syncthreads();
    }
    if (t == 0) out[g] = red[0] + bl2[0];
}

extern "C" void kernel_launch(void* const* d_in, const int* in_sizes, int n_in,
                              void* d_out, int out_size) {
    const float* x     = (const float*)d_in[0];
    const int*   hei   = (const int*)d_in[1];    // int32 (JAX x64-disabled)
    const int*   batch = (const int*)d_in[2];
    const float *W1  = (const float*)d_in[3],  *b1  = (const float*)d_in[4];
    const float *W2  = (const float*)d_in[5],  *b2  = (const float*)d_in[6];
    const float *W3  = (const float*)d_in[7],  *b3  = (const float*)d_in[8];
    const float *Wl1 = (const float*)d_in[9],  *bl1 = (const float*)d_in[10];
    const float *Wl2 = (const float*)d_in[11], *bl2 = (const float*)d_in[12];
    const int* nidx = hei;
    const int* eidx = hei + N_INC;
    float* out = (float*)d_out;

    // init + degrees  (launch indices 0..3)
    fill_init<<<1024, 256>>>();
    deg_k<<<(N_INC + 255) / 256, 256>>>(nidx, eidx);
    cnt_k<<<(N_NODES + 255) / 256, 256>>>(batch);
    inv_k<<<(N_NODES + 255) / 256, 256>>>();

    // ---- Layer 1 (scatter-first, dim 128; K=128 -> M=256) ----
    fillzero<<<4096, 256>>>(1, N_NODES * 128 / 4);                 // #4
    scat_n2e<<<N_INC / 8, 256>>>(x, -1, nidx, eidx, 5);            // #5 <- profiled
    fillzero<<<4096, 256>>>(0, N_NODES * 128 / 4);
    scat_e2n<<<N_INC / 8, 256>>>(0, nidx, eidx, 5);
    gemm_k<<<dim3(391, 2), 256>>>(nullptr, 0, W1, b1, 2, N_NODES, 128, 256, 1, 1);

    // ---- Layer 2 (scatter-first, dim 256; K=256 -> M=512) ----
    fillzero<<<4096, 256>>>(1, N_NODES * 256 / 4);
    scat_n2e<<<N_INC / 4, 256>>>(nullptr, 2, nidx, eidx, 6);
    fillzero<<<4096, 256>>>(0, N_NODES * 256 / 4);
    scat_e2n<<<N_INC / 4, 256>>>(0, nidx, eidx, 6);
    gemm_k<<<dim3(391, 4), 256>>>(nullptr, 0, W2, b2, 3, N_NODES, 256, 512, 1, 1);

    // ---- Layer 3 (gemm-first; K=512 -> M=256) ----
    gemm_k<<<dim3(391, 2), 256>>>(nullptr, 3, W3, nullptr, 0, N_NODES, 512, 256, 0, 0);
    fillzero<<<4096, 256>>>(1, N_NODES * 256 / 4);
    scat_n2e<<<N_INC / 4, 256>>>(nullptr, 0, nidx, eidx, 6);
    fillzero<<<4096, 256>>>(3, N_NODES * 256 / 4);
    scat_e2n<<<N_INC / 4, 256>>>(3, nidx, eidx, 6);
    act3_k<<<(N_NODES * 256 + 255) / 256, 256>>>(b3);

    // ---- pool + MLP ----
    pool_k<<<(N_NODES * 64 + 255) / 256, 256>>>(batch);
    mlp_k<<<N_GRAPHS, 256>>>(Wl1, bl1, Wl2, bl2, out);
}

// round 5
// speedup vs baseline: 2.2843x; 1.5699x over previous
#include <cuda_runtime.h>
#include <cstdint>

#define N_NODES  50000
#define N_EDGES  50000
#define N_GRAPHS 1024
#define N_INC    400000

// ---------------- scratch (device globals; device-side refs only) ----------------
__device__ float g_acc[N_NODES * 256];
__device__ float g_ef [N_NODES * 256];
__device__ float g_hA [N_NODES * 256];
__device__ float g_hB [N_NODES * 512];
__device__ float g_dinv[N_NODES];
__device__ float g_binv[N_EDGES];
__device__ float g_cnt [N_GRAPHS];
__device__ float g_pool[N_GRAPHS * 256];

__device__ __forceinline__ float* bufp(int s) {
    switch (s) {
        case 0: return g_acc;
        case 1: return g_ef;
        case 2: return g_hA;
        case 3: return g_hB;
        case 4: return g_dinv;
        case 5: return g_binv;
        case 6: return g_cnt;
        default: return g_pool;
    }
}

__device__ __forceinline__ void red4(float* p, float4 v) {
    asm volatile("red.global.v4.f32.add [%0], {%1,%2,%3,%4};"
                 :: "l"(p), "f"(v.x), "f"(v.y), "f"(v.z), "f"(v.w) : "memory");
}

__device__ __forceinline__ float tf32r(float f) {
    uint32_t u;
    asm("cvt.rna.tf32.f32 %0, %1;" : "=r"(u) : "f"(f));
    return __uint_as_float(u);
}

__device__ __forceinline__ void mma_tf32(float* c, const uint32_t* a, const uint32_t* b) {
    asm volatile(
        "mma.sync.aligned.m16n8k8.row.col.f32.tf32.tf32.f32 "
        "{%0,%1,%2,%3}, {%4,%5,%6,%7}, {%8,%9}, {%0,%1,%2,%3};"
        : "+f"(c[0]), "+f"(c[1]), "+f"(c[2]), "+f"(c[3])
        : "r"(a[0]), "r"(a[1]), "r"(a[2]), "r"(a[3]), "r"(b[0]), "r"(b[1]));
}

// ---------------- fills ----------------
__global__ void fill_init() {
    int i = blockIdx.x * 256 + threadIdx.x;
    if (i < N_NODES)        g_dinv[i] = 0.f;
    if (i < N_EDGES)        g_binv[i] = 0.f;
    if (i < N_GRAPHS)       g_cnt[i]  = 0.f;
    if (i < N_GRAPHS * 256) g_pool[i] = 0.f;
}

__global__ void fillzero(int sel, int n4) {
    float4* p = (float4*)bufp(sel);
    float4 z = make_float4(0.f, 0.f, 0.f, 0.f);
    for (int i = blockIdx.x * blockDim.x + threadIdx.x; i < n4;
         i += gridDim.x * blockDim.x)
        p[i] = z;
}

// ---------------- degree / count ----------------
__global__ void deg_k(const int* __restrict__ nidx, const int* __restrict__ eidx) {
    int i = blockIdx.x * blockDim.x + threadIdx.x;
    if (i < N_INC) {
        atomicAdd(&g_dinv[nidx[i]], 1.f);
        atomicAdd(&g_binv[eidx[i]], 1.f);
    }
}
__global__ void cnt_k(const int* __restrict__ batch) {
    int i = blockIdx.x * blockDim.x + threadIdx.x;
    if (i < N_NODES) atomicAdd(&g_cnt[batch[i]], 1.f);
}
__global__ void inv_k() {
    int i = blockIdx.x * blockDim.x + threadIdx.x;
    if (i < N_NODES) {
        float d = g_dinv[i]; g_dinv[i] = d > 0.f ? 1.f / d : 0.f;
        float b = g_binv[i]; g_binv[i] = b > 0.f ? 1.f / b : 0.f;
    }
}

// ---------------- scatters (vector atomics) ----------------
__global__ void scat_n2e(const float* __restrict__ inExt, int inSel,
                         const int* __restrict__ nidx, const int* __restrict__ eidx,
                         int log2q) {
    const float* in = (inSel >= 0) ? bufp(inSel) : inExt;
    const int t = threadIdx.x;
    const int q = 1 << log2q;
    const int j = t & (q - 1);
    const int i = blockIdx.x * (256 >> log2q) + (t >> log2q);
    const int dim = q << 2;
    const int n = nidx[i], e = eidx[i];
    float4 v = *(const float4*)(in + (size_t)n * dim + 4 * j);
    red4(&g_ef[(size_t)e * dim + 4 * j], v);
}

__global__ void scat_e2n(int outSel,
                         const int* __restrict__ nidx, const int* __restrict__ eidx,
                         int log2q) {
    float* outb = bufp(outSel);
    const int t = threadIdx.x;
    const int q = 1 << log2q;
    const int j = t & (q - 1);
    const int i = blockIdx.x * (256 >> log2q) + (t >> log2q);
    const int dim = q << 2;
    const int n = nidx[i], e = eidx[i];
    const float bw = g_binv[e];
    float4 v = *(const float4*)(g_ef + (size_t)e * dim + 4 * j);
    v.x *= bw; v.y *= bw; v.z *= bw; v.w *= bw;
    red4(&outb[(size_t)n * dim + 4 * j], v);
}

// ---------------- TF32 tensor-core GEMM -----------------------------------------
// C[N,M] = (scaleA? dinv⊙A : A)[N,K] @ W[K,M]; epi: bias+relu optional
// 128x128 block, BK=16, 8 warps (4m x 2n), warp tile 32x64 (2 x 8 mma tiles)
#define SB 136
__global__ void __launch_bounds__(256) gemm_tc(
    const float* __restrict__ Aext, int Asel, const float* __restrict__ W,
    const float* __restrict__ bias, int outSel,
    int N, int K, int M, int scaleA, int doEpi) {
    const float* A = (Asel >= 0) ? bufp(Asel) : Aext;
    float* C = bufp(outSel);

    __shared__ float As[16][SB];   // k-major: As[k][m]
    __shared__ float Bs[16][SB];   // Bs[k][n]

    const int tid  = threadIdx.x;
    const int lane = tid & 31;
    const int warp = tid >> 5;
    const int wm = (warp & 3) * 32;      // warp m offset in tile
    const int wn = (warp >> 2) * 64;     // warp n offset in tile
    const int grp = lane >> 2;           // 0..7
    const int tig = lane & 3;            // 0..3

    const int rowBase = blockIdx.x * 128;
    const int colBase = blockIdx.y * 128;

    // global->smem loader coords
    const int aRow = tid >> 1;           // 0..127
    const int aK   = (tid & 1) * 8;      // 0/8
    const int bRow = tid >> 4;           // 0..15
    const int bCol = (tid & 15) * 8;     // 0..120

    const int grow = rowBase + aRow;
    float ds = 1.f;
    if (scaleA) ds = (grow < N) ? g_dinv[grow] : 0.f;

    float acc[2][8][4];
#pragma unroll
    for (int mt = 0; mt < 2; mt++)
#pragma unroll
        for (int nt = 0; nt < 8; nt++)
#pragma unroll
            for (int r = 0; r < 4; r++) acc[mt][nt][r] = 0.f;

    const float4 z4 = make_float4(0.f, 0.f, 0.f, 0.f);
    float4 a0v = z4, a1v = z4;
    if (grow < N) {
        const float4* ap = (const float4*)(A + (size_t)grow * K + aK);
        a0v = ap[0]; a1v = ap[1];
    }
    const float4* bp = (const float4*)(W + (size_t)bRow * M + colBase + bCol);
    float4 b0v = bp[0], b1v = bp[1];

    for (int k0 = 0; k0 < K; k0 += 16) {
        // stage (with tf32 rounding fused)
        As[aK + 0][aRow] = tf32r(a0v.x * ds); As[aK + 1][aRow] = tf32r(a0v.y * ds);
        As[aK + 2][aRow] = tf32r(a0v.z * ds); As[aK + 3][aRow] = tf32r(a0v.w * ds);
        As[aK + 4][aRow] = tf32r(a1v.x * ds); As[aK + 5][aRow] = tf32r(a1v.y * ds);
        As[aK + 6][aRow] = tf32r(a1v.z * ds); As[aK + 7][aRow] = tf32r(a1v.w * ds);
        float4 c0 = make_float4(tf32r(b0v.x), tf32r(b0v.y), tf32r(b0v.z), tf32r(b0v.w));
        float4 c1 = make_float4(tf32r(b1v.x), tf32r(b1v.y), tf32r(b1v.z), tf32r(b1v.w));
        *(float4*)&Bs[bRow][bCol]     = c0;
        *(float4*)&Bs[bRow][bCol + 4] = c1;
        __syncthreads();

        if (k0 + 16 < K) {   // prefetch next stage
            a0v = z4; a1v = z4;
            if (grow < N) {
                const float4* ap = (const float4*)(A + (size_t)grow * K + k0 + 16 + aK);
                a0v = ap[0]; a1v = ap[1];
            }
            const float4* bq = (const float4*)(W + (size_t)(k0 + 16 + bRow) * M + colBase + bCol);
            b0v = bq[0]; b1v = bq[1];
        }

#pragma unroll
        for (int kk = 0; kk < 16; kk += 8) {
            uint32_t af[2][4], bf[8][2];
#pragma unroll
            for (int mt = 0; mt < 2; mt++) {
                const int mr = wm + mt * 16 + grp;
                af[mt][0] = __float_as_uint(As[kk + tig][mr]);
                af[mt][1] = __float_as_uint(As[kk + tig][mr + 8]);
                af[mt][2] = __float_as_uint(As[kk + tig + 4][mr]);
                af[mt][3] = __float_as_uint(As[kk + tig + 4][mr + 8]);
            }
#pragma unroll
            for (int nt = 0; nt < 8; nt++) {
                const int nc = wn + nt * 8 + grp;
                bf[nt][0] = __float_as_uint(Bs[kk + tig][nc]);
                bf[nt][1] = __float_as_uint(Bs[kk + tig + 4][nc]);
            }
#pragma unroll
            for (int mt = 0; mt < 2; mt++)
#pragma unroll
                for (int nt = 0; nt < 8; nt++)
                    mma_tf32(acc[mt][nt], af[mt], bf[nt]);
        }
        __syncthreads();
    }

    // epilogue: c0:(g, 2t) c1:(g, 2t+1) c2:(g+8, 2t) c3:(g+8, 2t+1)
#pragma unroll
    for (int mt = 0; mt < 2; mt++) {
        const int r0 = rowBase + wm + mt * 16 + grp;
        const int r1 = r0 + 8;
#pragma unroll
        for (int nt = 0; nt < 8; nt++) {
            const int col = colBase + wn + nt * 8 + tig * 2;
            float v0 = acc[mt][nt][0], v1 = acc[mt][nt][1];
            float v2 = acc[mt][nt][2], v3 = acc[mt][nt][3];
            if (doEpi) {
                const float bb0 = bias[col], bb1 = bias[col + 1];
                v0 = fmaxf(v0 + bb0, 0.f); v1 = fmaxf(v1 + bb1, 0.f);
                v2 = fmaxf(v2 + bb0, 0.f); v3 = fmaxf(v3 + bb1, 0.f);
            }
            if (r0 < N) *(float2*)(C + (size_t)r0 * M + col) = make_float2(v0, v1);
            if (r1 < N) *(float2*)(C + (size_t)r1 * M + col) = make_float2(v2, v3);
        }
    }
}

// ---------------- layer-3 epilogue: hA = relu(dinv * hB + b) --------------------
__global__ void act3_k(const float* __restrict__ bias) {
    int i = blockIdx.x * 256 + threadIdx.x;
    if (i >= N_NODES * 256) return;
    g_hA[i] = fmaxf(fmaf(g_dinv[i >> 8], g_hB[i], bias[i & 255]), 0.f);
}

// ---------------- global mean pool ----------------
__global__ void pool_k(const int* __restrict__ batch) {
    int i = blockIdx.x * 256 + threadIdx.x;
    if (i >= N_NODES * 64) return;
    int row = i >> 6;
    int j   = i & 63;
    float4 v = *(const float4*)(g_hA + (size_t)row * 256 + 4 * j);
    red4(&g_pool[(batch[row] << 8) + 4 * j], v);
}

// ---------------- final MLP ----------------
__global__ void __launch_bounds__(256) mlp_k(
    const float* __restrict__ Wl1, const float* __restrict__ bl1,
    const float* __restrict__ Wl2, const float* __restrict__ bl2,
    float* __restrict__ out) {
    __shared__ float sp[256];
    __shared__ float red[128];
    const int g = blockIdx.x;
    const int t = threadIdx.x;

    const float ic = 1.f / fmaxf(g_cnt[g], 1.f);
    sp[t] = g_pool[(g << 8) + t] * ic;
    __syncthreads();

    if (t < 128) {
        float a = bl1[t];
#pragma unroll 8
        for (int k = 0; k < 256; k++) a = fmaf(sp[k], Wl1[k * 128 + t], a);
        red[t] = fmaxf(a, 0.f) * Wl2[t];
    }
    __syncthreads();
    for (int s = 64; s > 0; s >>= 1) {
        if (t < s) red[t] += red[t + s];
        __syncthreads();
    }
    if (t == 0) out[g] = red[0] + bl2[0];
}

extern "C" void kernel_launch(void* const* d_in, const int* in_sizes, int n_in,
                              void* d_out, int out_size) {
    const float* x     = (const float*)d_in[0];
    const int*   hei   = (const int*)d_in[1];    // int32 (JAX x64-disabled)
    const int*   batch = (const int*)d_in[2];
    const float *W1  = (const float*)d_in[3],  *b1  = (const float*)d_in[4];
    const float *W2  = (const float*)d_in[5],  *b2  = (const float*)d_in[6];
    const float *W3  = (const float*)d_in[7],  *b3  = (const float*)d_in[8];
    const float *Wl1 = (const float*)d_in[9],  *bl1 = (const float*)d_in[10];
    const float *Wl2 = (const float*)d_in[11], *bl2 = (const float*)d_in[12];
    const int* nidx = hei;
    const int* eidx = hei + N_INC;
    float* out = (float*)d_out;

    fill_init<<<1024, 256>>>();
    deg_k<<<(N_INC + 255) / 256, 256>>>(nidx, eidx);
    cnt_k<<<(N_NODES + 255) / 256, 256>>>(batch);
    inv_k<<<(N_NODES + 255) / 256, 256>>>();

    // ---- Layer 1 (scatter-first, dim 128; K=128 -> M=256) ----
    fillzero<<<4096, 256>>>(1, N_NODES * 128 / 4);
    scat_n2e<<<N_INC / 8, 256>>>(x, -1, nidx, eidx, 5);
    fillzero<<<4096, 256>>>(0, N_NODES * 128 / 4);
    scat_e2n<<<N_INC / 8, 256>>>(0, nidx, eidx, 5);
    gemm_tc<<<dim3(391, 2), 256>>>(nullptr, 0, W1, b1, 2, N_NODES, 128, 256, 1, 1);

    // ---- Layer 2 (scatter-first, dim 256; K=256 -> M=512) ----
    fillzero<<<4096, 256>>>(1, N_NODES * 256 / 4);
    scat_n2e<<<N_INC / 4, 256>>>(nullptr, 2, nidx, eidx, 6);
    fillzero<<<4096, 256>>>(0, N_NODES * 256 / 4);
    scat_e2n<<<N_INC / 4, 256>>>(0, nidx, eidx, 6);
    gemm_tc<<<dim3(391, 4), 256>>>(nullptr, 0, W2, b2, 3, N_NODES, 256, 512, 1, 1);

    // ---- Layer 3 (gemm-first; K=512 -> M=256) ----
    gemm_tc<<<dim3(391, 2), 256>>>(nullptr, 3, W3, nullptr, 0, N_NODES, 512, 256, 0, 0);
    fillzero<<<4096, 256>>>(1, N_NODES * 256 / 4);
    scat_n2e<<<N_INC / 4, 256>>>(nullptr, 0, nidx, eidx, 6);
    fillzero<<<4096, 256>>>(3, N_NODES * 256 / 4);
    scat_e2n<<<N_INC / 4, 256>>>(3, nidx, eidx, 6);
    act3_k<<<(N_NODES * 256 + 255) / 256, 256>>>(b3);

    // ---- pool + MLP ----
    pool_k<<<(N_NODES * 64 + 255) / 256, 256>>>(batch);
    mlp_k<<<N_GRAPHS, 256>>>(Wl1, bl1, Wl2, bl2, out);
}

// round 6
// speedup vs baseline: 2.8029x; 1.2270x over previous
#include <cuda_runtime.h>
#include <cstdint>

#define N_NODES  50000
#define N_EDGES  50000
#define N_GRAPHS 1024
#define N_INC    400000

// ---------------- scratch (device globals; device-side refs only) ----------------
__device__ float g_acc[N_NODES * 256];
__device__ float g_ef [N_NODES * 256];
__device__ float g_hA [N_NODES * 256];
__device__ float g_hB [N_NODES * 512];
__device__ float g_dinv[N_NODES];
__device__ float g_binv[N_EDGES];
__device__ float g_cnt [N_GRAPHS];
__device__ float g_pool[N_GRAPHS * 256];

// CSR machinery
__device__ int g_degE[N_EDGES];     // edge degree counts
__device__ int g_degN[N_NODES];     // node degree counts
__device__ int g_offE[N_EDGES];     // exclusive prefix
__device__ int g_offN[N_NODES];
__device__ int g_curE[N_EDGES];     // placement cursors
__device__ int g_curN[N_NODES];
__device__ int g_nByE[N_INC];       // node ids grouped by edge
__device__ int g_eByN[N_INC];       // edge ids grouped by node

__device__ __forceinline__ float* bufp(int s) {
    switch (s) {
        case 0: return g_acc;
        case 1: return g_ef;
        case 2: return g_hA;
        case 3: return g_hB;
        default: return g_pool;
    }
}

__device__ __forceinline__ void red4(float* p, float4 v) {
    asm volatile("red.global.v4.f32.add [%0], {%1,%2,%3,%4};"
                 :: "l"(p), "f"(v.x), "f"(v.y), "f"(v.z), "f"(v.w) : "memory");
}

__device__ __forceinline__ float tf32r(float f) {
    uint32_t u;
    asm("cvt.rna.tf32.f32 %0, %1;" : "=r"(u) : "f"(f));
    return __uint_as_float(u);
}

__device__ __forceinline__ void mma_tf32(float* c, const uint32_t* a, const uint32_t* b) {
    asm volatile(
        "mma.sync.aligned.m16n8k8.row.col.f32.tf32.tf32.f32 "
        "{%0,%1,%2,%3}, {%4,%5,%6,%7}, {%8,%9}, {%0,%1,%2,%3};"
        : "+f"(c[0]), "+f"(c[1]), "+f"(c[2]), "+f"(c[3])
        : "r"(a[0]), "r"(a[1]), "r"(a[2]), "r"(a[3]), "r"(b[0]), "r"(b[1]));
}

// ---------------- init: zero counters / pool ----------------
__global__ void fill_init() {
    int i = blockIdx.x * 256 + threadIdx.x;   // grid covers 262144
    if (i < N_EDGES)        g_degE[i] = 0;
    if (i < N_NODES)        g_degN[i] = 0;
    if (i < N_GRAPHS)       g_cnt[i]  = 0.f;
    if (i < N_GRAPHS * 256) g_pool[i] = 0.f;
}

// ---------------- degree / count ----------------
__global__ void deg_k(const int* __restrict__ nidx, const int* __restrict__ eidx) {
    int i = blockIdx.x * blockDim.x + threadIdx.x;
    if (i < N_INC) {
        atomicAdd(&g_degN[nidx[i]], 1);
        atomicAdd(&g_degE[eidx[i]], 1);
    }
}
__global__ void cnt_k(const int* __restrict__ batch) {
    int i = blockIdx.x * blockDim.x + threadIdx.x;
    if (i < N_NODES) atomicAdd(&g_cnt[batch[i]], 1.f);
}
__global__ void inv_k() {
    int i = blockIdx.x * blockDim.x + threadIdx.x;
    if (i < N_NODES) {
        int dn = g_degN[i]; g_dinv[i] = dn > 0 ? 1.f / (float)dn : 0.f;
        int de = g_degE[i]; g_binv[i] = de > 0 ? 1.f / (float)de : 0.f;
    }
}

// ---------------- exclusive scan (1 block, 1024 threads, n<=50k) ----------------
__global__ void __launch_bounds__(1024) scan_k(int which) {
    const int* cnt = which ? g_degN : g_degE;
    int* offs      = which ? g_offN : g_offE;
    int* cur       = which ? g_curN : g_curE;
    const int n = which ? N_NODES : N_EDGES;

    __shared__ int part[1024];
    const int t = threadIdx.x;
    const int chunk = (n + 1023) >> 10;
    const int s0 = t * chunk;
    const int s1 = (s0 + chunk < n) ? s0 + chunk : n;

    int s = 0;
    for (int i = s0; i < s1; i++) s += cnt[i];
    part[t] = s;
    __syncthreads();
    for (int d = 1; d < 1024; d <<= 1) {
        int v = (t >= d) ? part[t - d] : 0;
        __syncthreads();
        part[t] += v;
        __syncthreads();
    }
    int run = (t > 0) ? part[t - 1] : 0;
    for (int i = s0; i < s1; i++) {
        offs[i] = run;
        cur[i]  = run;
        run += cnt[i];
    }
}

// ---------------- counting-sort placement ----------------
__global__ void build_k(const int* __restrict__ nidx, const int* __restrict__ eidx) {
    int i = blockIdx.x * blockDim.x + threadIdx.x;
    if (i >= N_INC) return;
    const int n = nidx[i], e = eidx[i];
    int pe = atomicAdd(&g_curE[e], 1);
    g_nByE[pe] = n;
    int pn = atomicAdd(&g_curN[n], 1);
    g_eByN[pn] = e;
}

// ---------------- gather n2e: ef[e] = binv[e] * sum_{n in e} in[n] -------------
// q = dim/4 float4 lanes; (256>>log2q) edges per block
__global__ void __launch_bounds__(256) gath_n2e(
    const float* __restrict__ inExt, int inSel, int log2q) {
    const float4* in = (const float4*)((inSel >= 0) ? bufp(inSel) : inExt);
    const int t = threadIdx.x;
    const int q = 1 << log2q;
    const int j = t & (q - 1);
    const int e = blockIdx.x * (256 >> log2q) + (t >> log2q);
    const int start = g_offE[e];
    const int d     = g_degE[e];
    float4 acc = make_float4(0.f, 0.f, 0.f, 0.f);
    for (int k = 0; k < d; k++) {
        const int n = g_nByE[start + k];
        float4 v = in[((size_t)n << log2q) + j];
        acc.x += v.x; acc.y += v.y; acc.z += v.z; acc.w += v.w;
    }
    const float bw = g_binv[e];
    acc.x *= bw; acc.y *= bw; acc.z *= bw; acc.w *= bw;
    ((float4*)g_ef)[((size_t)e << log2q) + j] = acc;
}

// ---------------- gather e2n: out[n] = dinv[n] * sum_{e of n} ef[e] (+epi) -----
__global__ void __launch_bounds__(256) gath_e2n(
    int outSel, int log2q, int doEpi, const float* __restrict__ bias) {
    float4* outb = (float4*)bufp(outSel);
    const int t = threadIdx.x;
    const int q = 1 << log2q;
    const int j = t & (q - 1);
    const int n = blockIdx.x * (256 >> log2q) + (t >> log2q);
    const int start = g_offN[n];
    const int d     = g_degN[n];
    float4 acc = make_float4(0.f, 0.f, 0.f, 0.f);
    for (int k = 0; k < d; k++) {
        const int e = g_eByN[start + k];
        float4 v = ((const float4*)g_ef)[((size_t)e << log2q) + j];
        acc.x += v.x; acc.y += v.y; acc.z += v.z; acc.w += v.w;
    }
    const float ds = g_dinv[n];
    acc.x *= ds; acc.y *= ds; acc.z *= ds; acc.w *= ds;
    if (doEpi) {
        float4 bb = ((const float4*)bias)[j];
        acc.x = fmaxf(acc.x + bb.x, 0.f); acc.y = fmaxf(acc.y + bb.y, 0.f);
        acc.z = fmaxf(acc.z + bb.z, 0.f); acc.w = fmaxf(acc.w + bb.w, 0.f);
    }
    outb[((size_t)n << log2q) + j] = acc;
}

// ---------------- TF32 tensor-core GEMM (128x128, BK=16, 8 warps) ---------------
#define SB 136
__global__ void __launch_bounds__(256) gemm_tc(
    const float* __restrict__ Aext, int Asel, const float* __restrict__ W,
    const float* __restrict__ bias, int outSel,
    int N, int K, int M, int doEpi) {
    const float* A = (Asel >= 0) ? bufp(Asel) : Aext;
    float* C = bufp(outSel);

    __shared__ float As[16][SB];
    __shared__ float Bs[16][SB];

    const int tid  = threadIdx.x;
    const int lane = tid & 31;
    const int warp = tid >> 5;
    const int wm = (warp & 3) * 32;
    const int wn = (warp >> 2) * 64;
    const int grp = lane >> 2;
    const int tig = lane & 3;

    const int rowBase = blockIdx.x * 128;
    const int colBase = blockIdx.y * 128;

    const int aRow = tid >> 1;
    const int aK   = (tid & 1) * 8;
    const int bRow = tid >> 4;
    const int bCol = (tid & 15) * 8;

    const int grow = rowBase + aRow;

    float acc[2][8][4];
#pragma unroll
    for (int mt = 0; mt < 2; mt++)
#pragma unroll
        for (int nt = 0; nt < 8; nt++)
#pragma unroll
            for (int r = 0; r < 4; r++) acc[mt][nt][r] = 0.f;

    const float4 z4 = make_float4(0.f, 0.f, 0.f, 0.f);
    float4 a0v = z4, a1v = z4;
    if (grow < N) {
        const float4* ap = (const float4*)(A + (size_t)grow * K + aK);
        a0v = ap[0]; a1v = ap[1];
    }
    const float4* bp = (const float4*)(W + (size_t)bRow * M + colBase + bCol);
    float4 b0v = bp[0], b1v = bp[1];

    for (int k0 = 0; k0 < K; k0 += 16) {
        As[aK + 0][aRow] = tf32r(a0v.x); As[aK + 1][aRow] = tf32r(a0v.y);
        As[aK + 2][aRow] = tf32r(a0v.z); As[aK + 3][aRow] = tf32r(a0v.w);
        As[aK + 4][aRow] = tf32r(a1v.x); As[aK + 5][aRow] = tf32r(a1v.y);
        As[aK + 6][aRow] = tf32r(a1v.z); As[aK + 7][aRow] = tf32r(a1v.w);
        float4 c0 = make_float4(tf32r(b0v.x), tf32r(b0v.y), tf32r(b0v.z), tf32r(b0v.w));
        float4 c1 = make_float4(tf32r(b1v.x), tf32r(b1v.y), tf32r(b1v.z), tf32r(b1v.w));
        *(float4*)&Bs[bRow][bCol]     = c0;
        *(float4*)&Bs[bRow][bCol + 4] = c1;
        __syncthreads();

        if (k0 + 16 < K) {
            a0v = z4; a1v = z4;
            if (grow < N) {
                const float4* ap = (const float4*)(A + (size_t)grow * K + k0 + 16 + aK);
                a0v = ap[0]; a1v = ap[1];
            }
            const float4* bq = (const float4*)(W + (size_t)(k0 + 16 + bRow) * M + colBase + bCol);
            b0v = bq[0]; b1v = bq[1];
        }

#pragma unroll
        for (int kk = 0; kk < 16; kk += 8) {
            uint32_t af[2][4], bf[8][2];
#pragma unroll
            for (int mt = 0; mt < 2; mt++) {
                const int mr = wm + mt * 16 + grp;
                af[mt][0] = __float_as_uint(As[kk + tig][mr]);
                af[mt][1] = __float_as_uint(As[kk + tig][mr + 8]);
                af[mt][2] = __float_as_uint(As[kk + tig + 4][mr]);
                af[mt][3] = __float_as_uint(As[kk + tig + 4][mr + 8]);
            }
#pragma unroll
            for (int nt = 0; nt < 8; nt++) {
                const int nc = wn + nt * 8 + grp;
                bf[nt][0] = __float_as_uint(Bs[kk + tig][nc]);
                bf[nt][1] = __float_as_uint(Bs[kk + tig + 4][nc]);
            }
#pragma unroll
            for (int mt = 0; mt < 2; mt++)
#pragma unroll
                for (int nt = 0; nt < 8; nt++)
                    mma_tf32(acc[mt][nt], af[mt], bf[nt]);
        }
        __syncthreads();
    }

#pragma unroll
    for (int mt = 0; mt < 2; mt++) {
        const int r0 = rowBase + wm + mt * 16 + grp;
        const int r1 = r0 + 8;
#pragma unroll
        for (int nt = 0; nt < 8; nt++) {
            const int col = colBase + wn + nt * 8 + tig * 2;
            float v0 = acc[mt][nt][0], v1 = acc[mt][nt][1];
            float v2 = acc[mt][nt][2], v3 = acc[mt][nt][3];
            if (doEpi) {
                const float bb0 = bias[col], bb1 = bias[col + 1];
                v0 = fmaxf(v0 + bb0, 0.f); v1 = fmaxf(v1 + bb1, 0.f);
                v2 = fmaxf(v2 + bb0, 0.f); v3 = fmaxf(v3 + bb1, 0.f);
            }
            if (r0 < N) *(float2*)(C + (size_t)r0 * M + col) = make_float2(v0, v1);
            if (r1 < N) *(float2*)(C + (size_t)r1 * M + col) = make_float2(v2, v3);
        }
    }
}

// ---------------- global mean pool ----------------
__global__ void pool_k(const int* __restrict__ batch) {
    int i = blockIdx.x * 256 + threadIdx.x;
    if (i >= N_NODES * 64) return;
    int row = i >> 6;
    int j   = i & 63;
    float4 v = *(const float4*)(g_hA + (size_t)row * 256 + 4 * j);
    red4(&g_pool[(batch[row] << 8) + 4 * j], v);
}

// ---------------- final MLP ----------------
__global__ void __launch_bounds__(256) mlp_k(
    const float* __restrict__ Wl1, const float* __restrict__ bl1,
    const float* __restrict__ Wl2, const float* __restrict__ bl2,
    float* __restrict__ out) {
    __shared__ float sp[256];
    __shared__ float red[128];
    const int g = blockIdx.x;
    const int t = threadIdx.x;

    const float ic = 1.f / fmaxf(g_cnt[g], 1.f);
    sp[t] = g_pool[(g << 8) + t] * ic;
    __syncthreads();

    if (t < 128) {
        float a = bl1[t];
#pragma unroll 8
        for (int k = 0; k < 256; k++) a = fmaf(sp[k], Wl1[k * 128 + t], a);
        red[t] = fmaxf(a, 0.f) * Wl2[t];
    }
    __syncthreads();
    for (int s = 64; s > 0; s >>= 1) {
        if (t < s) red[t] += red[t + s];
        __syncthreads();
    }
    if (t == 0) out[g] = red[0] + bl2[0];
}

extern "C" void kernel_launch(void* const* d_in, const int* in_sizes, int n_in,
                              void* d_out, int out_size) {
    const float* x     = (const float*)d_in[0];
    const int*   hei   = (const int*)d_in[1];    // int32 (JAX x64-disabled)
    const int*   batch = (const int*)d_in[2];
    const float *W1  = (const float*)d_in[3],  *b1  = (const float*)d_in[4];
    const float *W2  = (const float*)d_in[5],  *b2  = (const float*)d_in[6];
    const float *W3  = (const float*)d_in[7],  *b3  = (const float*)d_in[8];
    const float *Wl1 = (const float*)d_in[9],  *bl1 = (const float*)d_in[10];
    const float *Wl2 = (const float*)d_in[11], *bl2 = (const float*)d_in[12];
    const int* nidx = hei;
    const int* eidx = hei + N_INC;
    float* out = (float*)d_out;

    // ---- setup: degrees, scans, CSR build ----
    fill_init<<<1024, 256>>>();
    deg_k<<<(N_INC + 255) / 256, 256>>>(nidx, eidx);
    cnt_k<<<(N_NODES + 255) / 256, 256>>>(batch);
    scan_k<<<1, 1024>>>(0);   // edges
    scan_k<<<1, 1024>>>(1);   // nodes
    inv_k<<<(N_NODES + 255) / 256, 256>>>();
    build_k<<<(N_INC + 255) / 256, 256>>>(nidx, eidx);

    // ---- Layer 1 (gather-first, dim 128; K=128 -> M=256) ----
    gath_n2e<<<N_EDGES / 8, 256>>>(x, -1, 5);
    gath_e2n<<<N_NODES / 8, 256>>>(0, 5, 0, nullptr);
    gemm_tc<<<dim3(391, 2), 256>>>(nullptr, 0, W1, b1, 2, N_NODES, 128, 256, 1);

    // ---- Layer 2 (gather-first, dim 256; K=256 -> M=512) ----
    gath_n2e<<<N_EDGES / 4, 256>>>(nullptr, 2, 6);
    gath_e2n<<<N_NODES / 4, 256>>>(0, 6, 0, nullptr);
    gemm_tc<<<dim3(391, 4), 256>>>(nullptr, 0, W2, b2, 3, N_NODES, 256, 512, 1);

    // ---- Layer 3 (gemm-first; K=512 -> M=256; epi fused into e2n) ----
    gemm_tc<<<dim3(391, 2), 256>>>(nullptr, 3, W3, nullptr, 0, N_NODES, 512, 256, 0);
    gath_n2e<<<N_EDGES / 4, 256>>>(nullptr, 0, 6);
    gath_e2n<<<N_NODES / 4, 256>>>(2, 6, 1, b3);

    // ---- pool + MLP ----
    pool_k<<<(N_NODES * 64 + 255) / 256, 256>>>(batch);
    mlp_k<<<N_GRAPHS, 256>>>(Wl1, bl1, Wl2, bl2, out);
}

// round 7
// speedup vs baseline: 3.6013x; 1.2849x over previous
#include <cuda_runtime.h>
#include <cstdint>

#define N_NODES  50000
#define N_EDGES  50000
#define N_GRAPHS 1024
#define N_INC    400000
#define SCAN_B   196          // ceil(50000/256)

// ---------------- scratch (device globals; device-side refs only) ----------------
__device__ float g_acc[N_NODES * 256];
__device__ float g_ef [N_NODES * 256];
__device__ float g_hA [N_NODES * 256];
__device__ float g_hB [N_NODES * 512];
__device__ float g_dinv[N_NODES];
__device__ float g_binv[N_EDGES];
__device__ float g_cnt [N_GRAPHS];
__device__ float g_pool[N_GRAPHS * 256];

// CSR machinery
__device__ int g_degE[N_EDGES];
__device__ int g_degN[N_NODES];
__device__ int g_offE[N_EDGES];
__device__ int g_offN[N_NODES];
__device__ int g_curE[N_EDGES];
__device__ int g_curN[N_NODES];
__device__ int g_nByE[N_INC];
__device__ int g_eByN[N_INC];
__device__ int g_part[2][256];     // block partial sums (196 used per array)

__device__ __forceinline__ float* bufp(int s) {
    switch (s) {
        case 0: return g_acc;
        case 1: return g_ef;
        case 2: return g_hA;
        case 3: return g_hB;
        default: return g_pool;
    }
}

__device__ __forceinline__ void red4(float* p, float4 v) {
    asm volatile("red.global.v4.f32.add [%0], {%1,%2,%3,%4};"
                 :: "l"(p), "f"(v.x), "f"(v.y), "f"(v.z), "f"(v.w) : "memory");
}

__device__ __forceinline__ float tf32r(float f) {
    uint32_t u;
    asm("cvt.rna.tf32.f32 %0, %1;" : "=r"(u) : "f"(f));
    return __uint_as_float(u);
}

__device__ __forceinline__ void mma_tf32(float* c, const uint32_t* a, const uint32_t* b) {
    asm volatile(
        "mma.sync.aligned.m16n8k8.row.col.f32.tf32.tf32.f32 "
        "{%0,%1,%2,%3}, {%4,%5,%6,%7}, {%8,%9}, {%0,%1,%2,%3};"
        : "+f"(c[0]), "+f"(c[1]), "+f"(c[2]), "+f"(c[3])
        : "r"(a[0]), "r"(a[1]), "r"(a[2]), "r"(a[3]), "r"(b[0]), "r"(b[1]));
}

// ---------------- init: zero counters / pool ----------------
__global__ void fill_init() {
    int i = blockIdx.x * 256 + threadIdx.x;   // grid covers 262144
    if (i < N_EDGES)        g_degE[i] = 0;
    if (i < N_NODES)        g_degN[i] = 0;
    if (i < N_GRAPHS)       g_cnt[i]  = 0.f;
    if (i < N_GRAPHS * 256) g_pool[i] = 0.f;
}

// ---------------- degrees + graph counts (fused) ----------------
__global__ void degcnt_k(const int* __restrict__ nidx, const int* __restrict__ eidx,
                         const int* __restrict__ batch) {
    int i = blockIdx.x * blockDim.x + threadIdx.x;
    if (i < N_INC) {
        atomicAdd(&g_degN[nidx[i]], 1);
        atomicAdd(&g_degE[eidx[i]], 1);
    }
    if (i < N_NODES) atomicAdd(&g_cnt[batch[i]], 1.f);
}

__global__ void inv_k() {
    int i = blockIdx.x * blockDim.x + threadIdx.x;
    if (i < N_NODES) {
        int dn = g_degN[i]; g_dinv[i] = dn > 0 ? 1.f / (float)dn : 0.f;
        int de = g_degE[i]; g_binv[i] = de > 0 ? 1.f / (float)de : 0.f;
    }
}

// ---------------- 3-phase grid scan (blockIdx.y: 0=edges, 1=nodes) --------------
__global__ void __launch_bounds__(256) scan1_k() {
    __shared__ int sm[256];
    const int w = blockIdx.y;
    const int* cnt = w ? g_degN : g_degE;
    const int i = blockIdx.x * 256 + threadIdx.x;
    const int t = threadIdx.x;
    sm[t] = (i < N_EDGES) ? cnt[i] : 0;
    __syncthreads();
    for (int s = 128; s > 0; s >>= 1) {
        if (t < s) sm[t] += sm[t + s];
        __syncthreads();
    }
    if (t == 0) g_part[w][blockIdx.x] = sm[0];
}

__global__ void __launch_bounds__(256) scan2_k() {
    __shared__ int sm[256];
    const int t = threadIdx.x;
    for (int w = 0; w < 2; w++) {
        int v = (t < SCAN_B) ? g_part[w][t] : 0;
        sm[t] = v;
        __syncthreads();
        for (int d = 1; d < 256; d <<= 1) {
            int u = (t >= d) ? sm[t - d] : 0;
            __syncthreads();
            sm[t] += u;
            __syncthreads();
        }
        if (t < SCAN_B) g_part[w][t] = sm[t] - v;   // exclusive
        __syncthreads();
    }
}

__global__ void __launch_bounds__(256) scan3_k() {
    __shared__ int sm[256];
    const int w = blockIdx.y;
    const int* cnt = w ? g_degN : g_degE;
    int* offs = w ? g_offN : g_offE;
    int* cur  = w ? g_curN : g_curE;
    const int i = blockIdx.x * 256 + threadIdx.x;
    const int t = threadIdx.x;
    const int v = (i < N_EDGES) ? cnt[i] : 0;
    sm[t] = v;
    __syncthreads();
    for (int d = 1; d < 256; d <<= 1) {
        int u = (t >= d) ? sm[t - d] : 0;
        __syncthreads();
        sm[t] += u;
        __syncthreads();
    }
    if (i < N_EDGES) {
        int e = sm[t] - v + g_part[w][blockIdx.x];
        offs[i] = e;
        cur[i]  = e;
    }
}

// ---------------- counting-sort placement ----------------
__global__ void build_k(const int* __restrict__ nidx, const int* __restrict__ eidx) {
    int i = blockIdx.x * blockDim.x + threadIdx.x;
    if (i >= N_INC) return;
    const int n = nidx[i], e = eidx[i];
    int pe = atomicAdd(&g_curE[e], 1);
    g_nByE[pe] = n;
    int pn = atomicAdd(&g_curN[n], 1);
    g_eByN[pn] = e;
}

// ---------------- gather n2e: ef[e] = binv[e] * sum_{n in e} in[n] -------------
__global__ void __launch_bounds__(256) gath_n2e(
    const float* __restrict__ inExt, int inSel, int log2q) {
    const float4* in = (const float4*)((inSel >= 0) ? bufp(inSel) : inExt);
    const int t = threadIdx.x;
    const int q = 1 << log2q;
    const int j = t & (q - 1);
    const int e = blockIdx.x * (256 >> log2q) + (t >> log2q);
    const int start = g_offE[e];
    const int d     = g_degE[e];
    float4 acc = make_float4(0.f, 0.f, 0.f, 0.f);
    for (int k = 0; k < d; k++) {
        const int n = g_nByE[start + k];
        float4 v = in[((size_t)n << log2q) + j];
        acc.x += v.x; acc.y += v.y; acc.z += v.z; acc.w += v.w;
    }
    const float bw = g_binv[e];
    acc.x *= bw; acc.y *= bw; acc.z *= bw; acc.w *= bw;
    ((float4*)g_ef)[((size_t)e << log2q) + j] = acc;
}

// ---------------- gather e2n: out[n] = dinv[n] * sum_{e of n} ef[e] (+epi) -----
__global__ void __launch_bounds__(256) gath_e2n(
    int outSel, int log2q, int doEpi, const float* __restrict__ bias) {
    float4* outb = (float4*)bufp(outSel);
    const int t = threadIdx.x;
    const int q = 1 << log2q;
    const int j = t & (q - 1);
    const int n = blockIdx.x * (256 >> log2q) + (t >> log2q);
    const int start = g_offN[n];
    const int d     = g_degN[n];
    float4 acc = make_float4(0.f, 0.f, 0.f, 0.f);
    for (int k = 0; k < d; k++) {
        const int e = g_eByN[start + k];
        float4 v = ((const float4*)g_ef)[((size_t)e << log2q) + j];
        acc.x += v.x; acc.y += v.y; acc.z += v.z; acc.w += v.w;
    }
    const float ds = g_dinv[n];
    acc.x *= ds; acc.y *= ds; acc.z *= ds; acc.w *= ds;
    if (doEpi) {
        float4 bb = ((const float4*)bias)[j];
        acc.x = fmaxf(acc.x + bb.x, 0.f); acc.y = fmaxf(acc.y + bb.y, 0.f);
        acc.z = fmaxf(acc.z + bb.z, 0.f); acc.w = fmaxf(acc.w + bb.w, 0.f);
    }
    outb[((size_t)n << log2q) + j] = acc;
}

// ---------------- TF32 tensor-core GEMM (128x128, BK=16, 8 warps) ---------------
#define SB 136
__global__ void __launch_bounds__(256) gemm_tc(
    const float* __restrict__ Aext, int Asel, const float* __restrict__ W,
    const float* __restrict__ bias, int outSel,
    int N, int K, int M, int doEpi) {
    const float* A = (Asel >= 0) ? bufp(Asel) : Aext;
    float* C = bufp(outSel);

    __shared__ float As[16][SB];
    __shared__ float Bs[16][SB];

    const int tid  = threadIdx.x;
    const int lane = tid & 31;
    const int warp = tid >> 5;
    const int wm = (warp & 3) * 32;
    const int wn = (warp >> 2) * 64;
    const int grp = lane >> 2;
    const int tig = lane & 3;

    const int rowBase = blockIdx.x * 128;
    const int colBase = blockIdx.y * 128;

    const int aRow = tid >> 1;
    const int aK   = (tid & 1) * 8;
    const int bRow = tid >> 4;
    const int bCol = (tid & 15) * 8;

    const int grow = rowBase + aRow;

    float acc[2][8][4];
#pragma unroll
    for (int mt = 0; mt < 2; mt++)
#pragma unroll
        for (int nt = 0; nt < 8; nt++)
#pragma unroll
            for (int r = 0; r < 4; r++) acc[mt][nt][r] = 0.f;

    const float4 z4 = make_float4(0.f, 0.f, 0.f, 0.f);
    float4 a0v = z4, a1v = z4;
    if (grow < N) {
        const float4* ap = (const float4*)(A + (size_t)grow * K + aK);
        a0v = ap[0]; a1v = ap[1];
    }
    const float4* bp = (const float4*)(W + (size_t)bRow * M + colBase + bCol);
    float4 b0v = bp[0], b1v = bp[1];

    for (int k0 = 0; k0 < K; k0 += 16) {
        As[aK + 0][aRow] = tf32r(a0v.x); As[aK + 1][aRow] = tf32r(a0v.y);
        As[aK + 2][aRow] = tf32r(a0v.z); As[aK + 3][aRow] = tf32r(a0v.w);
        As[aK + 4][aRow] = tf32r(a1v.x); As[aK + 5][aRow] = tf32r(a1v.y);
        As[aK + 6][aRow] = tf32r(a1v.z); As[aK + 7][aRow] = tf32r(a1v.w);
        float4 c0 = make_float4(tf32r(b0v.x), tf32r(b0v.y), tf32r(b0v.z), tf32r(b0v.w));
        float4 c1 = make_float4(tf32r(b1v.x), tf32r(b1v.y), tf32r(b1v.z), tf32r(b1v.w));
        *(float4*)&Bs[bRow][bCol]     = c0;
        *(float4*)&Bs[bRow][bCol + 4] = c1;
        __syncthreads();

        if (k0 + 16 < K) {
            a0v = z4; a1v = z4;
            if (grow < N) {
                const float4* ap = (const float4*)(A + (size_t)grow * K + k0 + 16 + aK);
                a0v = ap[0]; a1v = ap[1];
            }
            const float4* bq = (const float4*)(W + (size_t)(k0 + 16 + bRow) * M + colBase + bCol);
            b0v = bq[0]; b1v = bq[1];
        }

#pragma unroll
        for (int kk = 0; kk < 16; kk += 8) {
            uint32_t af[2][4], bf[8][2];
#pragma unroll
            for (int mt = 0; mt < 2; mt++) {
                const int mr = wm + mt * 16 + grp;
                af[mt][0] = __float_as_uint(As[kk + tig][mr]);
                af[mt][1] = __float_as_uint(As[kk + tig][mr + 8]);
                af[mt][2] = __float_as_uint(As[kk + tig + 4][mr]);
                af[mt][3] = __float_as_uint(As[kk + tig + 4][mr + 8]);
            }
#pragma unroll
            for (int nt = 0; nt < 8; nt++) {
                const int nc = wn + nt * 8 + grp;
                bf[nt][0] = __float_as_uint(Bs[kk + tig][nc]);
                bf[nt][1] = __float_as_uint(Bs[kk + tig + 4][nc]);
            }
#pragma unroll
            for (int mt = 0; mt < 2; mt++)
#pragma unroll
                for (int nt = 0; nt < 8; nt++)
                    mma_tf32(acc[mt][nt], af[mt], bf[nt]);
        }
        __syncthreads();
    }

#pragma unroll
    for (int mt = 0; mt < 2; mt++) {
        const int r0 = rowBase + wm + mt * 16 + grp;
        const int r1 = r0 + 8;
#pragma unroll
        for (int nt = 0; nt < 8; nt++) {
            const int col = colBase + wn + nt * 8 + tig * 2;
            float v0 = acc[mt][nt][0], v1 = acc[mt][nt][1];
            float v2 = acc[mt][nt][2], v3 = acc[mt][nt][3];
            if (doEpi) {
                const float bb0 = bias[col], bb1 = bias[col + 1];
                v0 = fmaxf(v0 + bb0, 0.f); v1 = fmaxf(v1 + bb1, 0.f);
                v2 = fmaxf(v2 + bb0, 0.f); v3 = fmaxf(v3 + bb1, 0.f);
            }
            if (r0 < N) *(float2*)(C + (size_t)r0 * M + col) = make_float2(v0, v1);
            if (r1 < N) *(float2*)(C + (size_t)r1 * M + col) = make_float2(v2, v3);
        }
    }
}

// ---------------- global mean pool ----------------
__global__ void pool_k(const int* __restrict__ batch) {
    int i = blockIdx.x * 256 + threadIdx.x;
    if (i >= N_NODES * 64) return;
    int row = i >> 6;
    int j   = i & 63;
    float4 v = *(const float4*)(g_hA + (size_t)row * 256 + 4 * j);
    red4(&g_pool[(batch[row] << 8) + 4 * j], v);
}

// ---------------- final MLP ----------------
__global__ void __launch_bounds__(256) mlp_k(
    const float* __restrict__ Wl1, const float* __restrict__ bl1,
    const float* __restrict__ Wl2, const float* __restrict__ bl2,
    float* __restrict__ out) {
    __shared__ float sp[256];
    __shared__ float red[128];
    const int g = blockIdx.x;
    const int t = threadIdx.x;

    const float ic = 1.f / fmaxf(g_cnt[g], 1.f);
    sp[t] = g_pool[(g << 8) + t] * ic;
    __syncthreads();

    if (t < 128) {
        float a = bl1[t];
#pragma unroll 8
        for (int k = 0; k < 256; k++) a = fmaf(sp[k], Wl1[k * 128 + t], a);
        red[t] = fmaxf(a, 0.f) * Wl2[t];
    }
    __syncthreads();
    for (int s = 64; s > 0; s >>= 1) {
        if (t < s) red[t] += red[t + s];
        __syncthreads();
    }
    if (t == 0) out[g] = red[0] + bl2[0];
}

extern "C" void kernel_launch(void* const* d_in, const int* in_sizes, int n_in,
                              void* d_out, int out_size) {
    const float* x     = (const float*)d_in[0];
    const int*   hei   = (const int*)d_in[1];    // int32 (JAX x64-disabled)
    const int*   batch = (const int*)d_in[2];
    const float *W1  = (const float*)d_in[3],  *b1  = (const float*)d_in[4];
    const float *W2  = (const float*)d_in[5],  *b2  = (const float*)d_in[6];
    const float *W3  = (const float*)d_in[7],  *b3  = (const float*)d_in[8];
    const float *Wl1 = (const float*)d_in[9],  *bl1 = (const float*)d_in[10];
    const float *Wl2 = (const float*)d_in[11], *bl2 = (const float*)d_in[12];
    const int* nidx = hei;
    const int* eidx = hei + N_INC;
    float* out = (float*)d_out;

    // ---- setup: degrees, 3-phase scan, CSR build ----
    fill_init<<<1024, 256>>>();
    degcnt_k<<<(N_INC + 255) / 256, 256>>>(nidx, eidx, batch);
    scan1_k<<<dim3(SCAN_B, 2), 256>>>();
    scan2_k<<<1, 256>>>();
    scan3_k<<<dim3(SCAN_B, 2), 256>>>();
    inv_k<<<(N_NODES + 255) / 256, 256>>>();
    build_k<<<(N_INC + 255) / 256, 256>>>(nidx, eidx);

    // ---- Layer 1 (gather-first, dim 128; K=128 -> M=256) ----
    gath_n2e<<<N_EDGES / 8, 256>>>(x, -1, 5);
    gath_e2n<<<N_NODES / 8, 256>>>(0, 5, 0, nullptr);
    gemm_tc<<<dim3(391, 2), 256>>>(nullptr, 0, W1, b1, 2, N_NODES, 128, 256, 1);

    // ---- Layer 2 (gather-first, dim 256; K=256 -> M=512) ----
    gath_n2e<<<N_EDGES / 4, 256>>>(nullptr, 2, 6);
    gath_e2n<<<N_NODES / 4, 256>>>(0, 6, 0, nullptr);
    gemm_tc<<<dim3(391, 4), 256>>>(nullptr, 0, W2, b2, 3, N_NODES, 256, 512, 1);

    // ---- Layer 3 (gemm-first; K=512 -> M=256; epi fused into e2n) ----
    gemm_tc<<<dim3(391, 2), 256>>>(nullptr, 3, W3, nullptr, 0, N_NODES, 512, 256, 0);
    gath_n2e<<<N_EDGES / 4, 256>>>(nullptr, 0, 6);
    gath_e2n<<<N_NODES / 4, 256>>>(2, 6, 1, b3);

    // ---- pool + MLP ----
    pool_k<<<(N_NODES * 64 + 255) / 256, 256>>>(batch);
    mlp_k<<<N_GRAPHS, 256>>>(Wl1, bl1, Wl2, bl2, out);
}

// round 8
// speedup vs baseline: 5.2724x; 1.4640x over previous
#include <cuda_runtime.h>
#include <cuda_bf16.h>
#include <cstdint>

#define N_NODES  50000
#define N_EDGES  50000
#define N_GRAPHS 1024
#define N_INC    400000
#define SCAN_B   196          // ceil(50000/256)

typedef __nv_bfloat16  bf16;
typedef __nv_bfloat162 bf162;

// ---------------- scratch (device globals) ----------------
__device__ bf16 g_acc_h[N_NODES * 256];
__device__ bf16 g_ef_h [N_NODES * 256];
__device__ bf16 g_hA_h [N_NODES * 256];
__device__ bf16 g_hB_h [N_NODES * 512];
__device__ bf16 g_W1t[256 * 128];       // bf16 W transposed [M][K]
__device__ bf16 g_W2t[512 * 256];
__device__ bf16 g_W3t[256 * 512];
__device__ float g_dinv[N_NODES];
__device__ float g_binv[N_EDGES];
__device__ float g_cnt [N_GRAPHS];
__device__ float g_pool[N_GRAPHS * 256];

// CSR machinery
__device__ int g_degE[N_EDGES];
__device__ int g_degN[N_NODES];
__device__ int g_offE[N_EDGES];
__device__ int g_offN[N_NODES];
__device__ int g_curE[N_EDGES];
__device__ int g_curN[N_NODES];
__device__ int g_nByE[N_INC];
__device__ int g_eByN[N_INC];
__device__ int g_part[2][256];

__device__ __forceinline__ bf16* bufh(int s) {
    switch (s) {
        case 0: return g_acc_h;
        case 1: return g_ef_h;
        case 2: return g_hA_h;
        case 3: return g_hB_h;
        case 4: return g_W1t;
        case 5: return g_W2t;
        default: return g_W3t;
    }
}

__device__ __forceinline__ void red4(float* p, float4 v) {
    asm volatile("red.global.v4.f32.add [%0], {%1,%2,%3,%4};"
                 :: "l"(p), "f"(v.x), "f"(v.y), "f"(v.z), "f"(v.w) : "memory");
}

__device__ __forceinline__ void mma_bf16(float* c, const uint32_t* a, const uint32_t* b) {
    asm volatile(
        "mma.sync.aligned.m16n8k16.row.col.f32.bf16.bf16.f32 "
        "{%0,%1,%2,%3}, {%4,%5,%6,%7}, {%8,%9}, {%0,%1,%2,%3};"
        : "+f"(c[0]), "+f"(c[1]), "+f"(c[2]), "+f"(c[3])
        : "r"(a[0]), "r"(a[1]), "r"(a[2]), "r"(a[3]), "r"(b[0]), "r"(b[1]));
}

__device__ __forceinline__ void acc8(float* a, uint4 v) {
    float2 f;
    f = __bfloat1622float2(*(bf162*)&v.x); a[0] += f.x; a[1] += f.y;
    f = __bfloat1622float2(*(bf162*)&v.y); a[2] += f.x; a[3] += f.y;
    f = __bfloat1622float2(*(bf162*)&v.z); a[4] += f.x; a[5] += f.y;
    f = __bfloat1622float2(*(bf162*)&v.w); a[6] += f.x; a[7] += f.y;
}

__device__ __forceinline__ uint4 pack8(const float* a) {
    uint4 r;
    *(bf162*)&r.x = __float22bfloat162_rn(make_float2(a[0], a[1]));
    *(bf162*)&r.y = __float22bfloat162_rn(make_float2(a[2], a[3]));
    *(bf162*)&r.z = __float22bfloat162_rn(make_float2(a[4], a[5]));
    *(bf162*)&r.w = __float22bfloat162_rn(make_float2(a[6], a[7]));
    return r;
}

// ---------------- init / degrees / scans / build ----------------
__global__ void fill_init() {
    int i = blockIdx.x * 256 + threadIdx.x;
    if (i < N_EDGES)        g_degE[i] = 0;
    if (i < N_NODES)        g_degN[i] = 0;
    if (i < N_GRAPHS)       g_cnt[i]  = 0.f;
    if (i < N_GRAPHS * 256) g_pool[i] = 0.f;
}

__global__ void degcnt_k(const int* __restrict__ nidx, const int* __restrict__ eidx,
                         const int* __restrict__ batch) {
    int i = blockIdx.x * blockDim.x + threadIdx.x;
    if (i < N_INC) {
        atomicAdd(&g_degN[nidx[i]], 1);
        atomicAdd(&g_degE[eidx[i]], 1);
    }
    if (i < N_NODES) atomicAdd(&g_cnt[batch[i]], 1.f);
}

__global__ void inv_k() {
    int i = blockIdx.x * blockDim.x + threadIdx.x;
    if (i < N_NODES) {
        int dn = g_degN[i]; g_dinv[i] = dn > 0 ? 1.f / (float)dn : 0.f;
        int de = g_degE[i]; g_binv[i] = de > 0 ? 1.f / (float)de : 0.f;
    }
}

__global__ void __launch_bounds__(256) scan1_k() {
    __shared__ int sm[256];
    const int w = blockIdx.y;
    const int* cnt = w ? g_degN : g_degE;
    const int i = blockIdx.x * 256 + threadIdx.x;
    const int t = threadIdx.x;
    sm[t] = (i < N_EDGES) ? cnt[i] : 0;
    __syncthreads();
    for (int s = 128; s > 0; s >>= 1) {
        if (t < s) sm[t] += sm[t + s];
        __syncthreads();
    }
    if (t == 0) g_part[w][blockIdx.x] = sm[0];
}

__global__ void __launch_bounds__(256) scan2_k() {
    __shared__ int sm[256];
    const int t = threadIdx.x;
    for (int w = 0; w < 2; w++) {
        int v = (t < SCAN_B) ? g_part[w][t] : 0;
        sm[t] = v;
        __syncthreads();
        for (int d = 1; d < 256; d <<= 1) {
            int u = (t >= d) ? sm[t - d] : 0;
            __syncthreads();
            sm[t] += u;
            __syncthreads();
        }
        if (t < SCAN_B) g_part[w][t] = sm[t] - v;
        __syncthreads();
    }
}

__global__ void __launch_bounds__(256) scan3_k() {
    __shared__ int sm[256];
    const int w = blockIdx.y;
    const int* cnt = w ? g_degN : g_degE;
    int* offs = w ? g_offN : g_offE;
    int* cur  = w ? g_curN : g_curE;
    const int i = blockIdx.x * 256 + threadIdx.x;
    const int t = threadIdx.x;
    const int v = (i < N_EDGES) ? cnt[i] : 0;
    sm[t] = v;
    __syncthreads();
    for (int d = 1; d < 256; d <<= 1) {
        int u = (t >= d) ? sm[t - d] : 0;
        __syncthreads();
        sm[t] += u;
        __syncthreads();
    }
    if (i < N_EDGES) {
        int e = sm[t] - v + g_part[w][blockIdx.x];
        offs[i] = e;
        cur[i]  = e;
    }
}

__global__ void build_k(const int* __restrict__ nidx, const int* __restrict__ eidx) {
    int i = blockIdx.x * blockDim.x + threadIdx.x;
    if (i >= N_INC) return;
    const int n = nidx[i], e = eidx[i];
    int pe = atomicAdd(&g_curE[e], 1);
    g_nByE[pe] = n;
    int pn = atomicAdd(&g_curN[n], 1);
    g_eByN[pn] = e;
}

// ---------------- weight convert: dst[m*K+k] = bf16(W[k*M+m]) ----------------
__global__ void wconv_k(const float* __restrict__ W, int dstSel, int K, int M) {
    bf16* dst = bufh(dstSel);
    int i = blockIdx.x * 256 + threadIdx.x;
    if (i >= K * M) return;
    int m = i / K, k = i - m * K;
    dst[i] = __float2bfloat16(W[(size_t)k * M + m]);
}

// ---------------- gathers ----------------
// layer1 n2e: fp32 input x (dim 128), bf16 output
__global__ void __launch_bounds__(256) gath_n2e_f32(const float* __restrict__ x) {
    const int t = threadIdx.x;
    const int j = t & 31;                       // float4 slot (dim128 -> 32 slots)
    const int e = blockIdx.x * 8 + (t >> 5);
    const int start = g_offE[e];
    const int d     = g_degE[e];
    float4 acc = make_float4(0.f, 0.f, 0.f, 0.f);
    for (int k = 0; k < d; k++) {
        const int n = g_nByE[start + k];
        float4 v = ((const float4*)x)[(size_t)n * 32 + j];
        acc.x += v.x; acc.y += v.y; acc.z += v.z; acc.w += v.w;
    }
    const float bw = g_binv[e];
    uint2 r;
    *(bf162*)&r.x = __float22bfloat162_rn(make_float2(acc.x * bw, acc.y * bw));
    *(bf162*)&r.y = __float22bfloat162_rn(make_float2(acc.z * bw, acc.w * bw));
    *(uint2*)(g_ef_h + (size_t)e * 128 + 4 * j) = r;
}

// bf16 n2e: slots are uint4 = 8 bf16; log2q: dim128->4, dim256->5
__global__ void __launch_bounds__(256) gath_n2e_h(int inSel, int log2q) {
    const uint4* in = (const uint4*)bufh(inSel);
    const int t = threadIdx.x;
    const int j = t & ((1 << log2q) - 1);
    const int e = blockIdx.x * (256 >> log2q) + (t >> log2q);
    const int start = g_offE[e];
    const int d     = g_degE[e];
    float a[8] = {0.f, 0.f, 0.f, 0.f, 0.f, 0.f, 0.f, 0.f};
    for (int k = 0; k < d; k++) {
        const int n = g_nByE[start + k];
        acc8(a, in[((size_t)n << log2q) + j]);
    }
    const float bw = g_binv[e];
#pragma unroll
    for (int r = 0; r < 8; r++) a[r] *= bw;
    ((uint4*)g_ef_h)[((size_t)e << log2q) + j] = pack8(a);
}

__global__ void __launch_bounds__(256) gath_e2n_h(
    int outSel, int log2q, int doEpi, const float* __restrict__ bias) {
    uint4* outb = (uint4*)bufh(outSel);
    const uint4* ef = (const uint4*)g_ef_h;
    const int t = threadIdx.x;
    const int j = t & ((1 << log2q) - 1);
    const int n = blockIdx.x * (256 >> log2q) + (t >> log2q);
    const int start = g_offN[n];
    const int d     = g_degN[n];
    float a[8] = {0.f, 0.f, 0.f, 0.f, 0.f, 0.f, 0.f, 0.f};
    for (int k = 0; k < d; k++) {
        const int e = g_eByN[start + k];
        acc8(a, ef[((size_t)e << log2q) + j]);
    }
    const float ds = g_dinv[n];
#pragma unroll
    for (int r = 0; r < 8; r++) a[r] *= ds;
    if (doEpi) {
        float4 bb0 = ((const float4*)bias)[2 * j];
        float4 bb1 = ((const float4*)bias)[2 * j + 1];
        a[0] = fmaxf(a[0] + bb0.x, 0.f); a[1] = fmaxf(a[1] + bb0.y, 0.f);
        a[2] = fmaxf(a[2] + bb0.z, 0.f); a[3] = fmaxf(a[3] + bb0.w, 0.f);
        a[4] = fmaxf(a[4] + bb1.x, 0.f); a[5] = fmaxf(a[5] + bb1.y, 0.f);
        a[6] = fmaxf(a[6] + bb1.z, 0.f); a[7] = fmaxf(a[7] + bb1.w, 0.f);
    }
    outb[((size_t)n << log2q) + j] = pack8(a);
}

// ---------------- BF16 tensor-core GEMM -----------------------------------------
// C[N,M] = A[N,K] @ Wt[M,K]^T ; A, Wt, C all bf16; 128x128 tile, BK=32 bf16.
// smem rows: 16 uints (32 bf16) + 4 pad = stride 20 uints.
#define HS 20
__global__ void __launch_bounds__(256) gemm_bf(
    int Asel, int Wsel, const float* __restrict__ bias, int outSel,
    int N, int K, int M, int doEpi) {
    const bf16* A  = bufh(Asel);
    const bf16* Wt = bufh(Wsel);
    bf16* C = bufh(outSel);

    __shared__ uint32_t As_u[128 * HS];
    __shared__ uint32_t Bs_u[128 * HS];

    const int tid  = threadIdx.x;
    const int lane = tid & 31;
    const int warp = tid >> 5;
    const int wm = (warp & 3) * 32;
    const int wn = (warp >> 2) * 64;
    const int grp = lane >> 2;
    const int tig = lane & 3;

    const int rowBase = blockIdx.x * 128;
    const int colBase = blockIdx.y * 128;

    const int lr = tid >> 1;             // 0..127
    const int lk = (tid & 1) * 16;       // bf16 offset 0/16
    const int grow = rowBase + lr;
    const int gcol = colBase + lr;
    const int su = lr * HS + (lk >> 1);  // smem uint index

    float acc[2][8][4];
#pragma unroll
    for (int mt = 0; mt < 2; mt++)
#pragma unroll
        for (int nt = 0; nt < 8; nt++)
#pragma unroll
            for (int r = 0; r < 4; r++) acc[mt][nt][r] = 0.f;

    const uint4 z4 = make_uint4(0, 0, 0, 0);
    uint4 a0 = z4, a1 = z4;
    if (grow < N) {
        const uint4* ap = (const uint4*)(A + (size_t)grow * K + lk);
        a0 = ap[0]; a1 = ap[1];
    }
    const uint4* bp = (const uint4*)(Wt + (size_t)gcol * K + lk);
    uint4 b0 = bp[0], b1 = bp[1];

    for (int k0 = 0; k0 < K; k0 += 32) {
        *(uint4*)&As_u[su]     = a0;
        *(uint4*)&As_u[su + 4] = a1;
        *(uint4*)&Bs_u[su]     = b0;
        *(uint4*)&Bs_u[su + 4] = b1;
        __syncthreads();

        if (k0 + 32 < K) {
            a0 = z4; a1 = z4;
            if (grow < N) {
                const uint4* ap = (const uint4*)(A + (size_t)grow * K + k0 + 32 + lk);
                a0 = ap[0]; a1 = ap[1];
            }
            const uint4* bq = (const uint4*)(Wt + (size_t)gcol * K + k0 + 32 + lk);
            b0 = bq[0]; b1 = bq[1];
        }

#pragma unroll
        for (int kk2 = 0; kk2 < 16; kk2 += 8) {   // pair offset within 16 pairs
            uint32_t af[2][4], bfr[8][2];
#pragma unroll
            for (int mt = 0; mt < 2; mt++) {
                const int m = wm + mt * 16 + grp;
                af[mt][0] = As_u[m * HS + kk2 + tig];
                af[mt][1] = As_u[(m + 8) * HS + kk2 + tig];
                af[mt][2] = As_u[m * HS + kk2 + tig + 4];
                af[mt][3] = As_u[(m + 8) * HS + kk2 + tig + 4];
            }
#pragma unroll
            for (int nt = 0; nt < 8; nt++) {
                const int n = wn + nt * 8 + grp;
                bfr[nt][0] = Bs_u[n * HS + kk2 + tig];
                bfr[nt][1] = Bs_u[n * HS + kk2 + tig + 4];
            }
#pragma unroll
            for (int mt = 0; mt < 2; mt++)
#pragma unroll
                for (int nt = 0; nt < 8; nt++)
                    mma_bf16(acc[mt][nt], af[mt], bfr[nt]);
        }
        __syncthreads();
    }

#pragma unroll
    for (int mt = 0; mt < 2; mt++) {
        const int r0 = rowBase + wm + mt * 16 + grp;
        const int r1 = r0 + 8;
#pragma unroll
        for (int nt = 0; nt < 8; nt++) {
            const int col = colBase + wn + nt * 8 + tig * 2;
            float v0 = acc[mt][nt][0], v1 = acc[mt][nt][1];
            float v2 = acc[mt][nt][2], v3 = acc[mt][nt][3];
            if (doEpi) {
                const float bb0 = bias[col], bb1 = bias[col + 1];
                v0 = fmaxf(v0 + bb0, 0.f); v1 = fmaxf(v1 + bb1, 0.f);
                v2 = fmaxf(v2 + bb0, 0.f); v3 = fmaxf(v3 + bb1, 0.f);
            }
            if (r0 < N)
                *(bf162*)(C + (size_t)r0 * M + col) =
                    __float22bfloat162_rn(make_float2(v0, v1));
            if (r1 < N)
                *(bf162*)(C + (size_t)r1 * M + col) =
                    __float22bfloat162_rn(make_float2(v2, v3));
        }
    }
}

// ---------------- global mean pool (reads bf16 hA) ----------------
__global__ void pool_k(const int* __restrict__ batch) {
    int i = blockIdx.x * 256 + threadIdx.x;
    if (i >= N_NODES * 32) return;
    int row = i >> 5;
    int j   = i & 31;
    float a[8] = {0.f, 0.f, 0.f, 0.f, 0.f, 0.f, 0.f, 0.f};
    acc8(a, ((const uint4*)g_hA_h)[(size_t)row * 32 + j]);
    float* dst = &g_pool[(batch[row] << 8) + 8 * j];
    red4(dst,     make_float4(a[0], a[1], a[2], a[3]));
    red4(dst + 4, make_float4(a[4], a[5], a[6], a[7]));
}

// ---------------- final MLP ----------------
__global__ void __launch_bounds__(256) mlp_k(
    const float* __restrict__ Wl1, const float* __restrict__ bl1,
    const float* __restrict__ Wl2, const float* __restrict__ bl2,
    float* __restrict__ out) {
    __shared__ float sp[256];
    __shared__ float red[128];
    const int g = blockIdx.x;
    const int t = threadIdx.x;

    const float ic = 1.f / fmaxf(g_cnt[g], 1.f);
    sp[t] = g_pool[(g << 8) + t] * ic;
    __syncthreads();

    if (t < 128) {
        float a = bl1[t];
#pragma unroll 8
        for (int k = 0; k < 256; k++) a = fmaf(sp[k], Wl1[k * 128 + t], a);
        red[t] = fmaxf(a, 0.f) * Wl2[t];
    }
    __syncthreads();
    for (int s = 64; s > 0; s >>= 1) {
        if (t < s) red[t] += red[t + s];
        __syncthreads();
    }
    if (t == 0) out[g] = red[0] + bl2[0];
}

extern "C" void kernel_launch(void* const* d_in, const int* in_sizes, int n_in,
                              void* d_out, int out_size) {
    const float* x     = (const float*)d_in[0];
    const int*   hei   = (const int*)d_in[1];    // int32 (JAX x64-disabled)
    const int*   batch = (const int*)d_in[2];
    const float *W1  = (const float*)d_in[3],  *b1  = (const float*)d_in[4];
    const float *W2  = (const float*)d_in[5],  *b2  = (const float*)d_in[6];
    const float *W3  = (const float*)d_in[7],  *b3  = (const float*)d_in[8];
    const float *Wl1 = (const float*)d_in[9],  *bl1 = (const float*)d_in[10];
    const float *Wl2 = (const float*)d_in[11], *bl2 = (const float*)d_in[12];
    const int* nidx = hei;
    const int* eidx = hei + N_INC;
    float* out = (float*)d_out;

    // ---- setup ----
    fill_init<<<1024, 256>>>();
    degcnt_k<<<(N_INC + 255) / 256, 256>>>(nidx, eidx, batch);
    scan1_k<<<dim3(SCAN_B, 2), 256>>>();
    scan2_k<<<1, 256>>>();
    scan3_k<<<dim3(SCAN_B, 2), 256>>>();
    inv_k<<<(N_NODES + 255) / 256, 256>>>();
    build_k<<<(N_INC + 255) / 256, 256>>>(nidx, eidx);
    wconv_k<<<(256 * 128 + 255) / 256, 256>>>(W1, 4, 128, 256);
    wconv_k<<<(512 * 256 + 255) / 256, 256>>>(W2, 5, 256, 512);
    wconv_k<<<(256 * 512 + 255) / 256, 256>>>(W3, 6, 512, 256);

    // ---- Layer 1 (gather-first, dim 128; K=128 -> M=256) ----
    gath_n2e_f32<<<N_EDGES / 8, 256>>>(x);
    gath_e2n_h<<<N_NODES / 16, 256>>>(0, 4, 0, nullptr);
    gemm_bf<<<dim3(391, 2), 256>>>(0, 4, b1, 2, N_NODES, 128, 256, 1);

    // ---- Layer 2 (gather-first, dim 256; K=256 -> M=512) ----
    gath_n2e_h<<<N_EDGES / 8, 256>>>(2, 5);
    gath_e2n_h<<<N_NODES / 8, 256>>>(0, 5, 0, nullptr);
    gemm_bf<<<dim3(391, 4), 256>>>(0, 5, b2, 3, N_NODES, 256, 512, 1);

    // ---- Layer 3 (gemm-first; K=512 -> M=256; epi fused into e2n) ----
    gemm_bf<<<dim3(391, 2), 256>>>(3, 6, nullptr, 0, N_NODES, 512, 256, 0);
    gath_n2e_h<<<N_EDGES / 8, 256>>>(0, 5);
    gath_e2n_h<<<N_NODES / 8, 256>>>(2, 5, 1, b3);

    // ---- pool + MLP ----
    pool_k<<<(N_NODES * 32 + 255) / 256, 256>>>(batch);
    mlp_k<<<N_GRAPHS, 256>>>(Wl1, bl1, Wl2, bl2, out);
}

// round 9
// speedup vs baseline: 5.8485x; 1.1093x over previous
#include <cuda_runtime.h>
#include <cuda_bf16.h>
#include <cstdint>

#define N_NODES  50000
#define N_EDGES  50000
#define N_GRAPHS 1024
#define N_INC    400000
#define SCAN_B   196          // ceil(50000/256)

typedef __nv_bfloat16  bf16;
typedef __nv_bfloat162 bf162;

// ---------------- scratch (device globals) ----------------
__device__ bf16 g_acc_h[N_NODES * 256];
__device__ bf16 g_ef_h [N_NODES * 256];
__device__ bf16 g_hA_h [N_NODES * 256];
__device__ bf16 g_hB_h [N_NODES * 512];
__device__ bf16 g_W1t[256 * 128];       // bf16 W transposed [M][K]
__device__ bf16 g_W2t[512 * 256];
__device__ bf16 g_W3t[256 * 512];
__device__ bf16 g_xh [N_NODES * 128];   // bf16 copy of input x
__device__ float g_dinv[N_NODES];
__device__ float g_binv[N_EDGES];
__device__ float g_cnt [N_GRAPHS];
__device__ float g_pool[N_GRAPHS * 256];

// CSR machinery
__device__ int g_degE[N_EDGES];
__device__ int g_degN[N_NODES];
__device__ int g_offE[N_EDGES];
__device__ int g_offN[N_NODES];
__device__ int g_curE[N_EDGES];
__device__ int g_curN[N_NODES];
__device__ int g_nByE[N_INC];
__device__ int g_eByN[N_INC];
__device__ int g_part[2][256];

__device__ __forceinline__ bf16* bufh(int s) {
    switch (s) {
        case 0: return g_acc_h;
        case 1: return g_ef_h;
        case 2: return g_hA_h;
        case 3: return g_hB_h;
        case 4: return g_W1t;
        case 5: return g_W2t;
        case 6: return g_W3t;
        default: return g_xh;
    }
}

__device__ __forceinline__ void red4(float* p, float4 v) {
    asm volatile("red.global.v4.f32.add [%0], {%1,%2,%3,%4};"
                 :: "l"(p), "f"(v.x), "f"(v.y), "f"(v.z), "f"(v.w) : "memory");
}

__device__ __forceinline__ void mma_bf16(float* c, const uint32_t* a, const uint32_t* b) {
    asm volatile(
        "mma.sync.aligned.m16n8k16.row.col.f32.bf16.bf16.f32 "
        "{%0,%1,%2,%3}, {%4,%5,%6,%7}, {%8,%9}, {%0,%1,%2,%3};"
        : "+f"(c[0]), "+f"(c[1]), "+f"(c[2]), "+f"(c[3])
        : "r"(a[0]), "r"(a[1]), "r"(a[2]), "r"(a[3]), "r"(b[0]), "r"(b[1]));
}

__device__ __forceinline__ void cp16(uint32_t dst, const void* src, bool pred) {
    int sz = pred ? 16 : 0;
    asm volatile("cp.async.cg.shared.global [%0], [%1], 16, %2;"
                 :: "r"(dst), "l"(src), "r"(sz));
}
#define CP_COMMIT() asm volatile("cp.async.commit_group;")
#define CP_WAIT0()  asm volatile("cp.async.wait_group 0;")

__device__ __forceinline__ void acc8(float* a, uint4 v) {
    float2 f;
    f = __bfloat1622float2(*(bf162*)&v.x); a[0] += f.x; a[1] += f.y;
    f = __bfloat1622float2(*(bf162*)&v.y); a[2] += f.x; a[3] += f.y;
    f = __bfloat1622float2(*(bf162*)&v.z); a[4] += f.x; a[5] += f.y;
    f = __bfloat1622float2(*(bf162*)&v.w); a[6] += f.x; a[7] += f.y;
}

__device__ __forceinline__ uint4 pack8(const float* a) {
    uint4 r;
    *(bf162*)&r.x = __float22bfloat162_rn(make_float2(a[0], a[1]));
    *(bf162*)&r.y = __float22bfloat162_rn(make_float2(a[2], a[3]));
    *(bf162*)&r.z = __float22bfloat162_rn(make_float2(a[4], a[5]));
    *(bf162*)&r.w = __float22bfloat162_rn(make_float2(a[6], a[7]));
    return r;
}

// ---------------- init / degrees / scans / build ----------------
__global__ void fill_init() {
    int i = blockIdx.x * 256 + threadIdx.x;
    if (i < N_EDGES)        g_degE[i] = 0;
    if (i < N_NODES)        g_degN[i] = 0;
    if (i < N_GRAPHS)       g_cnt[i]  = 0.f;
    if (i < N_GRAPHS * 256) g_pool[i] = 0.f;
}

__global__ void degcnt_k(const int* __restrict__ nidx, const int* __restrict__ eidx,
                         const int* __restrict__ batch) {
    int i = blockIdx.x * blockDim.x + threadIdx.x;
    if (i < N_INC) {
        atomicAdd(&g_degN[nidx[i]], 1);
        atomicAdd(&g_degE[eidx[i]], 1);
    }
    if (i < N_NODES) atomicAdd(&g_cnt[batch[i]], 1.f);
}

__global__ void __launch_bounds__(256) scan1_k() {
    __shared__ int sm[256];
    const int w = blockIdx.y;
    const int* cnt = w ? g_degN : g_degE;
    const int i = blockIdx.x * 256 + threadIdx.x;
    const int t = threadIdx.x;
    sm[t] = (i < N_EDGES) ? cnt[i] : 0;
    __syncthreads();
    for (int s = 128; s > 0; s >>= 1) {
        if (t < s) sm[t] += sm[t + s];
        __syncthreads();
    }
    if (t == 0) g_part[w][blockIdx.x] = sm[0];
}

__global__ void __launch_bounds__(256) scan2_k() {
    __shared__ int sm[256];
    const int t = threadIdx.x;
    for (int w = 0; w < 2; w++) {
        int v = (t < SCAN_B) ? g_part[w][t] : 0;
        sm[t] = v;
        __syncthreads();
        for (int d = 1; d < 256; d <<= 1) {
            int u = (t >= d) ? sm[t - d] : 0;
            __syncthreads();
            sm[t] += u;
            __syncthreads();
        }
        if (t < SCAN_B) g_part[w][t] = sm[t] - v;
        __syncthreads();
    }
}

// scan3 + inverse degrees fused
__global__ void __launch_bounds__(256) scan3_k() {
    __shared__ int sm[256];
    const int w = blockIdx.y;
    const int* cnt = w ? g_degN : g_degE;
    int* offs = w ? g_offN : g_offE;
    int* cur  = w ? g_curN : g_curE;
    float* invb = w ? g_dinv : g_binv;
    const int i = blockIdx.x * 256 + threadIdx.x;
    const int t = threadIdx.x;
    const int v = (i < N_EDGES) ? cnt[i] : 0;
    sm[t] = v;
    __syncthreads();
    for (int d = 1; d < 256; d <<= 1) {
        int u = (t >= d) ? sm[t - d] : 0;
        __syncthreads();
        sm[t] += u;
        __syncthreads();
    }
    if (i < N_EDGES) {
        int e = sm[t] - v + g_part[w][blockIdx.x];
        offs[i] = e;
        cur[i]  = e;
        invb[i] = v > 0 ? 1.f / (float)v : 0.f;
    }
}

__global__ void build_k(const int* __restrict__ nidx, const int* __restrict__ eidx) {
    int i = blockIdx.x * blockDim.x + threadIdx.x;
    if (i >= N_INC) return;
    const int n = nidx[i], e = eidx[i];
    int pe = atomicAdd(&g_curE[e], 1);
    g_nByE[pe] = n;
    int pn = atomicAdd(&g_curN[n], 1);
    g_eByN[pn] = e;
}

// ---------------- conversions: W1t, W2t, W3t (transposed) + xh ------------------
#define CONV_W1  (256 * 128)
#define CONV_W2  (512 * 256)
#define CONV_W3  (256 * 512)
#define CONV_X   (N_NODES * 128)
#define CONV_TOT (CONV_W1 + CONV_W2 + CONV_W3 + CONV_X)
__global__ void conv_all(const float* __restrict__ W1, const float* __restrict__ W2,
                         const float* __restrict__ W3, const float* __restrict__ x) {
    int i = blockIdx.x * 256 + threadIdx.x;
    if (i >= CONV_TOT) return;
    if (i < CONV_W1) {
        int m = i >> 7, k = i & 127;
        g_W1t[i] = __float2bfloat16(W1[k * 256 + m]);
    } else if (i < CONV_W1 + CONV_W2) {
        int j = i - CONV_W1;
        int m = j >> 8, k = j & 255;
        g_W2t[j] = __float2bfloat16(W2[k * 512 + m]);
    } else if (i < CONV_W1 + CONV_W2 + CONV_W3) {
        int j = i - CONV_W1 - CONV_W2;
        int m = j >> 9, k = j & 511;
        g_W3t[j] = __float2bfloat16(W3[k * 256 + m]);
    } else {
        int j = i - CONV_W1 - CONV_W2 - CONV_W3;
        g_xh[j] = __float2bfloat16(x[j]);
    }
}

// ---------------- gathers (bf16, 2-way unrolled) ----------------
__global__ void __launch_bounds__(256) gath_n2e_h(int inSel, int log2q) {
    const uint4* in = (const uint4*)bufh(inSel);
    const int t = threadIdx.x;
    const int j = t & ((1 << log2q) - 1);
    const int e = blockIdx.x * (256 >> log2q) + (t >> log2q);
    const int start = g_offE[e];
    const int d     = g_degE[e];
    float a[8] = {0.f, 0.f, 0.f, 0.f, 0.f, 0.f, 0.f, 0.f};
    int k = 0;
    for (; k + 1 < d; k += 2) {
        const int n0 = g_nByE[start + k];
        const int n1 = g_nByE[start + k + 1];
        uint4 v0 = in[((size_t)n0 << log2q) + j];
        uint4 v1 = in[((size_t)n1 << log2q) + j];
        acc8(a, v0);
        acc8(a, v1);
    }
    if (k < d) acc8(a, in[((size_t)g_nByE[start + k] << log2q) + j]);
    const float bw = g_binv[e];
#pragma unroll
    for (int r = 0; r < 8; r++) a[r] *= bw;
    ((uint4*)g_ef_h)[((size_t)e << log2q) + j] = pack8(a);
}

__global__ void __launch_bounds__(256) gath_e2n_h(
    int outSel, int log2q, int doEpi, const float* __restrict__ bias,
    int doPool, const int* __restrict__ batch) {
    uint4* outb = (uint4*)bufh(outSel);
    const uint4* ef = (const uint4*)g_ef_h;
    const int t = threadIdx.x;
    const int j = t & ((1 << log2q) - 1);
    const int n = blockIdx.x * (256 >> log2q) + (t >> log2q);
    const int start = g_offN[n];
    const int d     = g_degN[n];
    float a[8] = {0.f, 0.f, 0.f, 0.f, 0.f, 0.f, 0.f, 0.f};
    int k = 0;
    for (; k + 1 < d; k += 2) {
        const int e0 = g_eByN[start + k];
        const int e1 = g_eByN[start + k + 1];
        uint4 v0 = ef[((size_t)e0 << log2q) + j];
        uint4 v1 = ef[((size_t)e1 << log2q) + j];
        acc8(a, v0);
        acc8(a, v1);
    }
    if (k < d) acc8(a, ef[((size_t)g_eByN[start + k] << log2q) + j]);
    const float ds = g_dinv[n];
#pragma unroll
    for (int r = 0; r < 8; r++) a[r] *= ds;
    if (doEpi) {
        float4 bb0 = ((const float4*)bias)[2 * j];
        float4 bb1 = ((const float4*)bias)[2 * j + 1];
        a[0] = fmaxf(a[0] + bb0.x, 0.f); a[1] = fmaxf(a[1] + bb0.y, 0.f);
        a[2] = fmaxf(a[2] + bb0.z, 0.f); a[3] = fmaxf(a[3] + bb0.w, 0.f);
        a[4] = fmaxf(a[4] + bb1.x, 0.f); a[5] = fmaxf(a[5] + bb1.y, 0.f);
        a[6] = fmaxf(a[6] + bb1.z, 0.f); a[7] = fmaxf(a[7] + bb1.w, 0.f);
    }
    if (doPool) {
        float* dst = &g_pool[(batch[n] << 8) + 8 * j];
        red4(dst,     make_float4(a[0], a[1], a[2], a[3]));
        red4(dst + 4, make_float4(a[4], a[5], a[6], a[7]));
    } else {
        outb[((size_t)n << log2q) + j] = pack8(a);
    }
}

// ---------------- BF16 tensor-core GEMM, cp.async 2-stage pipeline --------------
// C[N,M] = A[N,K] @ Wt[M,K]^T; 128x128 tile, BK=32 bf16, 8 warps (4m x 2n).
#define HS 20                          // smem row stride in uints (64B data + 16B pad)
#define STAGE_U (128 * HS)             // uints per stage per matrix
__global__ void __launch_bounds__(256) gemm_bf(
    int Asel, int Wsel, const float* __restrict__ bias, int outSel,
    int N, int K, int M, int doEpi) {
    const bf16* A  = bufh(Asel);
    const bf16* Wt = bufh(Wsel);
    bf16* C = bufh(outSel);

    __shared__ uint32_t As_u[2][STAGE_U];
    __shared__ uint32_t Bs_u[2][STAGE_U];

    const int tid  = threadIdx.x;
    const int lane = tid & 31;
    const int warp = tid >> 5;
    const int wm = (warp & 3) * 32;
    const int wn = (warp >> 2) * 64;
    const int grp = lane >> 2;
    const int tig = lane & 3;

    const int rowBase = blockIdx.x * 128;
    const int colBase = blockIdx.y * 128;

    const int lr  = tid >> 1;              // 0..127
    const int lkb = (tid & 1) * 32;        // byte offset within 64B row stage
    const int grow = rowBase + lr;
    const int gcol = colBase + lr;
    const bool aok = grow < N;

    uint32_t aBase = (uint32_t)__cvta_generic_to_shared(&As_u[0][0]) + lr * 80 + lkb;
    uint32_t bBase = (uint32_t)__cvta_generic_to_shared(&Bs_u[0][0]) + lr * 80 + lkb;
    const char* aSrc0 = (const char*)(A + (size_t)(aok ? grow : 0) * K) + lkb;
    const char* bSrc0 = (const char*)(Wt + (size_t)gcol * K) + lkb;

    float acc[2][8][4];
#pragma unroll
    for (int mt = 0; mt < 2; mt++)
#pragma unroll
        for (int nt = 0; nt < 8; nt++)
#pragma unroll
            for (int r = 0; r < 4; r++) acc[mt][nt][r] = 0.f;

    const int nst = K >> 5;                // stages of 32 bf16 = 64B
    // prologue: stage 0
    cp16(aBase,      aSrc0,      aok);
    cp16(aBase + 16, aSrc0 + 16, aok);
    cp16(bBase,      bSrc0,      true);
    cp16(bBase + 16, bSrc0 + 16, true);
    CP_COMMIT();

    for (int i = 0; i < nst; i++) {
        CP_WAIT0();
        __syncthreads();
        if (i + 1 < nst) {
            const int s = (i + 1) & 1;
            const int off = (i + 1) * 64;  // bytes along K
            cp16(aBase + s * (STAGE_U * 4),      aSrc0 + off,      aok);
            cp16(aBase + s * (STAGE_U * 4) + 16, aSrc0 + off + 16, aok);
            cp16(bBase + s * (STAGE_U * 4),      bSrc0 + off,      true);
            cp16(bBase + s * (STAGE_U * 4) + 16, bSrc0 + off + 16, true);
            CP_COMMIT();
        }
        const uint32_t* Ab = As_u[i & 1];
        const uint32_t* Bb = Bs_u[i & 1];
#pragma unroll
        for (int kk2 = 0; kk2 < 16; kk2 += 8) {
            uint32_t af[2][4], bfr[8][2];
#pragma unroll
            for (int mt = 0; mt < 2; mt++) {
                const int m = wm + mt * 16 + grp;
                af[mt][0] = Ab[m * HS + kk2 + tig];
                af[mt][1] = Ab[(m + 8) * HS + kk2 + tig];
                af[mt][2] = Ab[m * HS + kk2 + tig + 4];
                af[mt][3] = Ab[(m + 8) * HS + kk2 + tig + 4];
            }
#pragma unroll
            for (int nt = 0; nt < 8; nt++) {
                const int n = wn + nt * 8 + grp;
                bfr[nt][0] = Bb[n * HS + kk2 + tig];
                bfr[nt][1] = Bb[n * HS + kk2 + tig + 4];
            }
#pragma unroll
            for (int mt = 0; mt < 2; mt++)
#pragma unroll
                for (int nt = 0; nt < 8; nt++)
                    mma_bf16(acc[mt][nt], af[mt], bfr[nt]);
        }
        __syncthreads();
    }

#pragma unroll
    for (int mt = 0; mt < 2; mt++) {
        const int r0 = rowBase + wm + mt * 16 + grp;
        const int r1 = r0 + 8;
#pragma unroll
        for (int nt = 0; nt < 8; nt++) {
            const int col = colBase + wn + nt * 8 + tig * 2;
            float v0 = acc[mt][nt][0], v1 = acc[mt][nt][1];
            float v2 = acc[mt][nt][2], v3 = acc[mt][nt][3];
            if (doEpi) {
                const float bb0 = bias[col], bb1 = bias[col + 1];
                v0 = fmaxf(v0 + bb0, 0.f); v1 = fmaxf(v1 + bb1, 0.f);
                v2 = fmaxf(v2 + bb0, 0.f); v3 = fmaxf(v3 + bb1, 0.f);
            }
            if (r0 < N)
                *(bf162*)(C + (size_t)r0 * M + col) =
                    __float22bfloat162_rn(make_float2(v0, v1));
            if (r1 < N)
                *(bf162*)(C + (size_t)r1 * M + col) =
                    __float22bfloat162_rn(make_float2(v2, v3));
        }
    }
}

// ---------------- final MLP ----------------
__global__ void __launch_bounds__(256) mlp_k(
    const float* __restrict__ Wl1, const float* __restrict__ bl1,
    const float* __restrict__ Wl2, const float* __restrict__ bl2,
    float* __restrict__ out) {
    __shared__ float sp[256];
    __shared__ float red[128];
    const int g = blockIdx.x;
    const int t = threadIdx.x;

    const float ic = 1.f / fmaxf(g_cnt[g], 1.f);
    sp[t] = g_pool[(g << 8) + t] * ic;
    __syncthreads();

    if (t < 128) {
        float a = bl1[t];
#pragma unroll 8
        for (int k = 0; k < 256; k++) a = fmaf(sp[k], Wl1[k * 128 + t], a);
        red[t] = fmaxf(a, 0.f) * Wl2[t];
    }
    __syncthreads();
    for (int s = 64; s > 0; s >>= 1) {
        if (t < s) red[t] += red[t + s];
        __syncthreads();
    }
    if (t == 0) out[g] = red[0] + bl2[0];
}

extern "C" void kernel_launch(void* const* d_in, const int* in_sizes, int n_in,
                              void* d_out, int out_size) {
    const float* x     = (const float*)d_in[0];
    const int*   hei   = (const int*)d_in[1];    // int32 (JAX x64-disabled)
    const int*   batch = (const int*)d_in[2];
    const float *W1  = (const float*)d_in[3],  *b1  = (const float*)d_in[4];
    const float *W2  = (const float*)d_in[5],  *b2  = (const float*)d_in[6];
    const float *W3  = (const float*)d_in[7],  *b3  = (const float*)d_in[8];
    const float *Wl1 = (const float*)d_in[9],  *bl1 = (const float*)d_in[10];
    const float *Wl2 = (const float*)d_in[11], *bl2 = (const float*)d_in[12];
    const int* nidx = hei;
    const int* eidx = hei + N_INC;
    float* out = (float*)d_out;

    // ---- setup ----
    fill_init<<<1024, 256>>>();
    degcnt_k<<<(N_INC + 255) / 256, 256>>>(nidx, eidx, batch);
    scan1_k<<<dim3(SCAN_B, 2), 256>>>();
    scan2_k<<<1, 256>>>();
    scan3_k<<<dim3(SCAN_B, 2), 256>>>();
    build_k<<<(N_INC + 255) / 256, 256>>>(nidx, eidx);
    conv_all<<<(CONV_TOT + 255) / 256, 256>>>(W1, W2, W3, x);

    // ---- Layer 1 (gather-first, dim 128 bf16; K=128 -> M=256) ----
    gath_n2e_h<<<N_EDGES / 16, 256>>>(7, 4);
    gath_e2n_h<<<N_NODES / 16, 256>>>(0, 4, 0, nullptr, 0, nullptr);
    gemm_bf<<<dim3(391, 2), 256>>>(0, 4, b1, 2, N_NODES, 128, 256, 1);

    // ---- Layer 2 (gather-first, dim 256; K=256 -> M=512) ----
    gath_n2e_h<<<N_EDGES / 8, 256>>>(2, 5);
    gath_e2n_h<<<N_NODES / 8, 256>>>(0, 5, 0, nullptr, 0, nullptr);
    gemm_bf<<<dim3(391, 4), 256>>>(0, 5, b2, 3, N_NODES, 256, 512, 1);

    // ---- Layer 3 (gemm-first; K=512 -> M=256; epi + pool fused into e2n) ----
    gemm_bf<<<dim3(391, 2), 256>>>(3, 6, nullptr, 0, N_NODES, 512, 256, 0);
    gath_n2e_h<<<N_EDGES / 8, 256>>>(0, 5);
    gath_e2n_h<<<N_NODES / 8, 256>>>(2, 5, 1, b3, 1, batch);

    // ---- MLP head ----
    mlp_k<<<N_GRAPHS, 256>>>(Wl1, bl1, Wl2, bl2, out);
}

// round 10
// speedup vs baseline: 6.0231x; 1.0299x over previous
#include <cuda_runtime.h>
#include <cuda_bf16.h>
#include <cstdint>

#define N_NODES  50000
#define N_EDGES  50000
#define N_GRAPHS 1024
#define N_INC    400000
#define SCAN_B   196          // ceil(50000/256)

typedef __nv_bfloat16  bf16;
typedef __nv_bfloat162 bf162;

// ---------------- scratch (device globals) ----------------
__device__ bf16 g_acc_h[N_NODES * 256];
__device__ bf16 g_ef_h [N_NODES * 256];
__device__ bf16 g_hA_h [N_NODES * 256];
__device__ bf16 g_hB_h [N_NODES * 512];
__device__ bf16 g_W1t[256 * 128];       // bf16 W transposed [M][K]
__device__ bf16 g_W2t[512 * 256];
__device__ bf16 g_W3t[256 * 512];
__device__ bf16 g_xh [N_NODES * 128];   // bf16 copy of input x
__device__ float g_dinv[N_NODES];
__device__ float g_binv[N_EDGES];
__device__ float g_cnt [N_GRAPHS];
__device__ float g_pool[N_GRAPHS * 256];

// CSR machinery
__device__ int g_degE[N_EDGES];
__device__ int g_degN[N_NODES];
__device__ int g_offE[N_EDGES];
__device__ int g_offN[N_NODES];
__device__ int g_curE[N_EDGES];
__device__ int g_curN[N_NODES];
__device__ int g_nByE[N_INC];
__device__ int g_eByN[N_INC];
__device__ int g_part[2][256];

__device__ __forceinline__ bf16* bufh(int s) {
    switch (s) {
        case 0: return g_acc_h;
        case 1: return g_ef_h;
        case 2: return g_hA_h;
        case 3: return g_hB_h;
        case 4: return g_W1t;
        case 5: return g_W2t;
        case 6: return g_W3t;
        default: return g_xh;
    }
}

__device__ __forceinline__ void red4(float* p, float4 v) {
    asm volatile("red.global.v4.f32.add [%0], {%1,%2,%3,%4};"
                 :: "l"(p), "f"(v.x), "f"(v.y), "f"(v.z), "f"(v.w) : "memory");
}

__device__ __forceinline__ void mma_bf16(float* c, const uint32_t* a, const uint32_t* b) {
    asm volatile(
        "mma.sync.aligned.m16n8k16.row.col.f32.bf16.bf16.f32 "
        "{%0,%1,%2,%3}, {%4,%5,%6,%7}, {%8,%9}, {%0,%1,%2,%3};"
        : "+f"(c[0]), "+f"(c[1]), "+f"(c[2]), "+f"(c[3])
        : "r"(a[0]), "r"(a[1]), "r"(a[2]), "r"(a[3]), "r"(b[0]), "r"(b[1]));
}

__device__ __forceinline__ void ldsm4(uint32_t* r, uint32_t addr) {
    asm volatile("ldmatrix.sync.aligned.m8n8.x4.shared.b16 {%0,%1,%2,%3}, [%4];"
                 : "=r"(r[0]), "=r"(r[1]), "=r"(r[2]), "=r"(r[3]) : "r"(addr));
}

__device__ __forceinline__ void cp16(uint32_t dst, const void* src, bool pred) {
    int sz = pred ? 16 : 0;
    asm volatile("cp.async.cg.shared.global [%0], [%1], 16, %2;"
                 :: "r"(dst), "l"(src), "r"(sz));
}
#define CP_COMMIT() asm volatile("cp.async.commit_group;")
#define CP_WAIT0()  asm volatile("cp.async.wait_group 0;")

__device__ __forceinline__ void acc8(float* a, uint4 v) {
    float2 f;
    f = __bfloat1622float2(*(bf162*)&v.x); a[0] += f.x; a[1] += f.y;
    f = __bfloat1622float2(*(bf162*)&v.y); a[2] += f.x; a[3] += f.y;
    f = __bfloat1622float2(*(bf162*)&v.z); a[4] += f.x; a[5] += f.y;
    f = __bfloat1622float2(*(bf162*)&v.w); a[6] += f.x; a[7] += f.y;
}

__device__ __forceinline__ uint4 pack8(const float* a) {
    uint4 r;
    *(bf162*)&r.x = __float22bfloat162_rn(make_float2(a[0], a[1]));
    *(bf162*)&r.y = __float22bfloat162_rn(make_float2(a[2], a[3]));
    *(bf162*)&r.z = __float22bfloat162_rn(make_float2(a[4], a[5]));
    *(bf162*)&r.w = __float22bfloat162_rn(make_float2(a[6], a[7]));
    return r;
}

// ---------------- init / degrees / scans / build ----------------
__global__ void fill_init() {
    int i = blockIdx.x * 256 + threadIdx.x;
    if (i < N_EDGES)        g_degE[i] = 0;
    if (i < N_NODES)        g_degN[i] = 0;
    if (i < N_GRAPHS)       g_cnt[i]  = 0.f;
    if (i < N_GRAPHS * 256) g_pool[i] = 0.f;
}

__global__ void degcnt_k(const int* __restrict__ nidx, const int* __restrict__ eidx,
                         const int* __restrict__ batch) {
    int i = blockIdx.x * blockDim.x + threadIdx.x;
    if (i < N_INC) {
        atomicAdd(&g_degN[nidx[i]], 1);
        atomicAdd(&g_degE[eidx[i]], 1);
    }
    if (i < N_NODES) atomicAdd(&g_cnt[batch[i]], 1.f);
}

__global__ void __launch_bounds__(256) scan1_k() {
    __shared__ int sm[256];
    const int w = blockIdx.y;
    const int* cnt = w ? g_degN : g_degE;
    const int i = blockIdx.x * 256 + threadIdx.x;
    const int t = threadIdx.x;
    sm[t] = (i < N_EDGES) ? cnt[i] : 0;
    __syncthreads();
    for (int s = 128; s > 0; s >>= 1) {
        if (t < s) sm[t] += sm[t + s];
        __syncthreads();
    }
    if (t == 0) g_part[w][blockIdx.x] = sm[0];
}

__global__ void __launch_bounds__(256) scan2_k() {
    __shared__ int sm[256];
    const int t = threadIdx.x;
    for (int w = 0; w < 2; w++) {
        int v = (t < SCAN_B) ? g_part[w][t] : 0;
        sm[t] = v;
        __syncthreads();
        for (int d = 1; d < 256; d <<= 1) {
            int u = (t >= d) ? sm[t - d] : 0;
            __syncthreads();
            sm[t] += u;
            __syncthreads();
        }
        if (t < SCAN_B) g_part[w][t] = sm[t] - v;
        __syncthreads();
    }
}

// scan3 + inverse degrees fused
__global__ void __launch_bounds__(256) scan3_k() {
    __shared__ int sm[256];
    const int w = blockIdx.y;
    const int* cnt = w ? g_degN : g_degE;
    int* offs = w ? g_offN : g_offE;
    int* cur  = w ? g_curN : g_curE;
    float* invb = w ? g_dinv : g_binv;
    const int i = blockIdx.x * 256 + threadIdx.x;
    const int t = threadIdx.x;
    const int v = (i < N_EDGES) ? cnt[i] : 0;
    sm[t] = v;
    __syncthreads();
    for (int d = 1; d < 256; d <<= 1) {
        int u = (t >= d) ? sm[t - d] : 0;
        __syncthreads();
        sm[t] += u;
        __syncthreads();
    }
    if (i < N_EDGES) {
        int e = sm[t] - v + g_part[w][blockIdx.x];
        offs[i] = e;
        cur[i]  = e;
        invb[i] = v > 0 ? 1.f / (float)v : 0.f;
    }
}

__global__ void build_k(const int* __restrict__ nidx, const int* __restrict__ eidx) {
    int i = blockIdx.x * blockDim.x + threadIdx.x;
    if (i >= N_INC) return;
    const int n = nidx[i], e = eidx[i];
    int pe = atomicAdd(&g_curE[e], 1);
    g_nByE[pe] = n;
    int pn = atomicAdd(&g_curN[n], 1);
    g_eByN[pn] = e;
}

// ---------------- conversions ----------------
#define CONV_W1  (256 * 128)
#define CONV_W2  (512 * 256)
#define CONV_W3  (256 * 512)
#define CONV_X   (N_NODES * 128)
#define CONV_TOT (CONV_W1 + CONV_W2 + CONV_W3 + CONV_X)
__global__ void conv_all(const float* __restrict__ W1, const float* __restrict__ W2,
                         const float* __restrict__ W3, const float* __restrict__ x) {
    int i = blockIdx.x * 256 + threadIdx.x;
    if (i >= CONV_TOT) return;
    if (i < CONV_W1) {
        int m = i >> 7, k = i & 127;
        g_W1t[i] = __float2bfloat16(W1[k * 256 + m]);
    } else if (i < CONV_W1 + CONV_W2) {
        int j = i - CONV_W1;
        int m = j >> 8, k = j & 255;
        g_W2t[j] = __float2bfloat16(W2[k * 512 + m]);
    } else if (i < CONV_W1 + CONV_W2 + CONV_W3) {
        int j = i - CONV_W1 - CONV_W2;
        int m = j >> 9, k = j & 511;
        g_W3t[j] = __float2bfloat16(W3[k * 256 + m]);
    } else {
        int j = i - CONV_W1 - CONV_W2 - CONV_W3;
        g_xh[j] = __float2bfloat16(x[j]);
    }
}

// ---------------- gathers (bf16, 4-way unrolled, __ldg) ----------------
__global__ void __launch_bounds__(256) gath_n2e_h(int inSel, int log2q) {
    const uint4* in = (const uint4*)bufh(inSel);
    const int t = threadIdx.x;
    const int j = t & ((1 << log2q) - 1);
    const int e = blockIdx.x * (256 >> log2q) + (t >> log2q);
    const int start = g_offE[e];
    const int d     = g_degE[e];
    float a[8] = {0.f, 0.f, 0.f, 0.f, 0.f, 0.f, 0.f, 0.f};
    int k = 0;
    for (; k + 3 < d; k += 4) {
        const int n0 = __ldg(&g_nByE[start + k]);
        const int n1 = __ldg(&g_nByE[start + k + 1]);
        const int n2 = __ldg(&g_nByE[start + k + 2]);
        const int n3 = __ldg(&g_nByE[start + k + 3]);
        uint4 v0 = __ldg(&in[((size_t)n0 << log2q) + j]);
        uint4 v1 = __ldg(&in[((size_t)n1 << log2q) + j]);
        uint4 v2 = __ldg(&in[((size_t)n2 << log2q) + j]);
        uint4 v3 = __ldg(&in[((size_t)n3 << log2q) + j]);
        acc8(a, v0); acc8(a, v1); acc8(a, v2); acc8(a, v3);
    }
    for (; k < d; k++)
        acc8(a, __ldg(&in[((size_t)__ldg(&g_nByE[start + k]) << log2q) + j]));
    const float bw = g_binv[e];
#pragma unroll
    for (int r = 0; r < 8; r++) a[r] *= bw;
    ((uint4*)g_ef_h)[((size_t)e << log2q) + j] = pack8(a);
}

__global__ void __launch_bounds__(256) gath_e2n_h(
    int outSel, int log2q, int doEpi, const float* __restrict__ bias,
    int doPool, const int* __restrict__ batch) {
    uint4* outb = (uint4*)bufh(outSel);
    const uint4* ef = (const uint4*)g_ef_h;
    const int t = threadIdx.x;
    const int j = t & ((1 << log2q) - 1);
    const int n = blockIdx.x * (256 >> log2q) + (t >> log2q);
    const int start = g_offN[n];
    const int d     = g_degN[n];
    float a[8] = {0.f, 0.f, 0.f, 0.f, 0.f, 0.f, 0.f, 0.f};
    int k = 0;
    for (; k + 3 < d; k += 4) {
        const int e0 = __ldg(&g_eByN[start + k]);
        const int e1 = __ldg(&g_eByN[start + k + 1]);
        const int e2 = __ldg(&g_eByN[start + k + 2]);
        const int e3 = __ldg(&g_eByN[start + k + 3]);
        uint4 v0 = __ldg(&ef[((size_t)e0 << log2q) + j]);
        uint4 v1 = __ldg(&ef[((size_t)e1 << log2q) + j]);
        uint4 v2 = __ldg(&ef[((size_t)e2 << log2q) + j]);
        uint4 v3 = __ldg(&ef[((size_t)e3 << log2q) + j]);
        acc8(a, v0); acc8(a, v1); acc8(a, v2); acc8(a, v3);
    }
    for (; k < d; k++)
        acc8(a, __ldg(&ef[((size_t)__ldg(&g_eByN[start + k]) << log2q) + j]));
    const float ds = g_dinv[n];
#pragma unroll
    for (int r = 0; r < 8; r++) a[r] *= ds;
    if (doEpi) {
        float4 bb0 = ((const float4*)bias)[2 * j];
        float4 bb1 = ((const float4*)bias)[2 * j + 1];
        a[0] = fmaxf(a[0] + bb0.x, 0.f); a[1] = fmaxf(a[1] + bb0.y, 0.f);
        a[2] = fmaxf(a[2] + bb0.z, 0.f); a[3] = fmaxf(a[3] + bb0.w, 0.f);
        a[4] = fmaxf(a[4] + bb1.x, 0.f); a[5] = fmaxf(a[5] + bb1.y, 0.f);
        a[6] = fmaxf(a[6] + bb1.z, 0.f); a[7] = fmaxf(a[7] + bb1.w, 0.f);
    }
    if (doPool) {
        float* dst = &g_pool[(batch[n] << 8) + 8 * j];
        red4(dst,     make_float4(a[0], a[1], a[2], a[3]));
        red4(dst + 4, make_float4(a[4], a[5], a[6], a[7]));
    } else {
        outb[((size_t)n << log2q) + j] = pack8(a);
    }
}

// ---------------- BF16 tensor-core GEMM, cp.async 2-stage + ldmatrix ------------
// C[N,M] = A[N,K] @ Wt[M,K]^T; 128x128 tile, BK=32 bf16, 8 warps (4m x 2n).
#define HS 20                          // smem row stride in uints (64B data + 16B pad)
#define STAGE_U (128 * HS)
#define STAGE_BYTES (STAGE_U * 4)
__global__ void __launch_bounds__(256) gemm_bf(
    int Asel, int Wsel, const float* __restrict__ bias, int outSel,
    int N, int K, int M, int doEpi) {
    const bf16* A  = bufh(Asel);
    const bf16* Wt = bufh(Wsel);
    bf16* C = bufh(outSel);

    __shared__ uint32_t As_u[2][STAGE_U];
    __shared__ uint32_t Bs_u[2][STAGE_U];

    const int tid  = threadIdx.x;
    const int lane = tid & 31;
    const int warp = tid >> 5;
    const int wm = (warp & 3) * 32;
    const int wn = (warp >> 2) * 64;
    const int grp = lane >> 2;
    const int tig = lane & 3;

    const int rowBase = blockIdx.x * 128;
    const int colBase = blockIdx.y * 128;

    const int lr  = tid >> 1;
    const int lkb = (tid & 1) * 32;
    const int grow = rowBase + lr;
    const int gcol = colBase + lr;
    const bool aok = grow < N;

    uint32_t smA = (uint32_t)__cvta_generic_to_shared(&As_u[0][0]);
    uint32_t smB = (uint32_t)__cvta_generic_to_shared(&Bs_u[0][0]);
    uint32_t aBase = smA + lr * 80 + lkb;
    uint32_t bBase = smB + lr * 80 + lkb;
    const char* aSrc0 = (const char*)(A + (size_t)(aok ? grow : 0) * K) + lkb;
    const char* bSrc0 = (const char*)(Wt + (size_t)gcol * K) + lkb;

    // ldmatrix addresses (uints -> bytes)
    uint32_t aAddr[2], bAddr[4];
#pragma unroll
    for (int mt = 0; mt < 2; mt++) {
        int row = wm + mt * 16 + ((lane >> 3) & 1) * 8 + (lane & 7);
        aAddr[mt] = smA + (row * HS + (lane >> 4) * 4) * 4;
    }
#pragma unroll
    for (int p = 0; p < 4; p++) {
        int row = wn + p * 16 + ((lane >> 4) & 1) * 8 + (lane & 7);
        bAddr[p] = smB + (row * HS + ((lane >> 3) & 1) * 4) * 4;
    }

    float acc[2][8][4];
#pragma unroll
    for (int mt = 0; mt < 2; mt++)
#pragma unroll
        for (int nt = 0; nt < 8; nt++)
#pragma unroll
            for (int r = 0; r < 4; r++) acc[mt][nt][r] = 0.f;

    const int nst = K >> 5;
    cp16(aBase,      aSrc0,      aok);
    cp16(aBase + 16, aSrc0 + 16, aok);
    cp16(bBase,      bSrc0,      true);
    cp16(bBase + 16, bSrc0 + 16, true);
    CP_COMMIT();

    for (int i = 0; i < nst; i++) {
        CP_WAIT0();
        __syncthreads();
        if (i + 1 < nst) {
            const int s = (i + 1) & 1;
            const int off = (i + 1) * 64;
            cp16(aBase + s * STAGE_BYTES,      aSrc0 + off,      aok);
            cp16(aBase + s * STAGE_BYTES + 16, aSrc0 + off + 16, aok);
            cp16(bBase + s * STAGE_BYTES,      bSrc0 + off,      true);
            cp16(bBase + s * STAGE_BYTES + 16, bSrc0 + off + 16, true);
            CP_COMMIT();
        }
        const uint32_t stOff = (i & 1) * STAGE_BYTES;
#pragma unroll
        for (int kk2 = 0; kk2 < 16; kk2 += 8) {
            const uint32_t kOff = stOff + kk2 * 4;
            uint32_t af[2][4], bq[4][4];
#pragma unroll
            for (int mt = 0; mt < 2; mt++) ldsm4(af[mt], aAddr[mt] + kOff);
#pragma unroll
            for (int p = 0; p < 4; p++)    ldsm4(bq[p],  bAddr[p] + kOff);
#pragma unroll
            for (int mt = 0; mt < 2; mt++)
#pragma unroll
                for (int p = 0; p < 4; p++) {
                    mma_bf16(acc[mt][2 * p],     af[mt], &bq[p][0]);
                    mma_bf16(acc[mt][2 * p + 1], af[mt], &bq[p][2]);
                }
        }
        __syncthreads();
    }

#pragma unroll
    for (int mt = 0; mt < 2; mt++) {
        const int r0 = rowBase + wm + mt * 16 + grp;
        const int r1 = r0 + 8;
#pragma unroll
        for (int nt = 0; nt < 8; nt++) {
            const int col = colBase + wn + nt * 8 + tig * 2;
            float v0 = acc[mt][nt][0], v1 = acc[mt][nt][1];
            float v2 = acc[mt][nt][2], v3 = acc[mt][nt][3];
            if (doEpi) {
                const float bb0 = bias[col], bb1 = bias[col + 1];
                v0 = fmaxf(v0 + bb0, 0.f); v1 = fmaxf(v1 + bb1, 0.f);
                v2 = fmaxf(v2 + bb0, 0.f); v3 = fmaxf(v3 + bb1, 0.f);
            }
            if (r0 < N)
                *(bf162*)(C + (size_t)r0 * M + col) =
                    __float22bfloat162_rn(make_float2(v0, v1));
            if (r1 < N)
                *(bf162*)(C + (size_t)r1 * M + col) =
                    __float22bfloat162_rn(make_float2(v2, v3));
        }
    }
}

// ---------------- final MLP ----------------
__global__ void __launch_bounds__(256) mlp_k(
    const float* __restrict__ Wl1, const float* __restrict__ bl1,
    const float* __restrict__ Wl2, const float* __restrict__ bl2,
    float* __restrict__ out) {
    __shared__ float sp[256];
    __shared__ float red[128];
    const int g = blockIdx.x;
    const int t = threadIdx.x;

    const float ic = 1.f / fmaxf(g_cnt[g], 1.f);
    sp[t] = g_pool[(g << 8) + t] * ic;
    __syncthreads();

    if (t < 128) {
        float a = bl1[t];
#pragma unroll 8
        for (int k = 0; k < 256; k++) a = fmaf(sp[k], Wl1[k * 128 + t], a);
        red[t] = fmaxf(a, 0.f) * Wl2[t];
    }
    __syncthreads();
    for (int s = 64; s > 0; s >>= 1) {
        if (t < s) red[t] += red[t + s];
        __syncthreads();
    }
    if (t == 0) out[g] = red[0] + bl2[0];
}

extern "C" void kernel_launch(void* const* d_in, const int* in_sizes, int n_in,
                              void* d_out, int out_size) {
    const float* x     = (const float*)d_in[0];
    const int*   hei   = (const int*)d_in[1];    // int32 (JAX x64-disabled)
    const int*   batch = (const int*)d_in[2];
    const float *W1  = (const float*)d_in[3],  *b1  = (const float*)d_in[4];
    const float *W2  = (const float*)d_in[5],  *b2  = (const float*)d_in[6];
    const float *W3  = (const float*)d_in[7],  *b3  = (const float*)d_in[8];
    const float *Wl1 = (const float*)d_in[9],  *bl1 = (const float*)d_in[10];
    const float *Wl2 = (const float*)d_in[11], *bl2 = (const float*)d_in[12];
    const int* nidx = hei;
    const int* eidx = hei + N_INC;
    float* out = (float*)d_out;

    // ---- setup ----
    fill_init<<<1024, 256>>>();
    degcnt_k<<<(N_INC + 255) / 256, 256>>>(nidx, eidx, batch);
    scan1_k<<<dim3(SCAN_B, 2), 256>>>();
    scan2_k<<<1, 256>>>();
    scan3_k<<<dim3(SCAN_B, 2), 256>>>();
    build_k<<<(N_INC + 255) / 256, 256>>>(nidx, eidx);
    conv_all<<<(CONV_TOT + 255) / 256, 256>>>(W1, W2, W3, x);

    // ---- Layer 1 (gather-first, dim 128 bf16; K=128 -> M=256) ----
    gath_n2e_h<<<N_EDGES / 16, 256>>>(7, 4);
    gath_e2n_h<<<N_NODES / 16, 256>>>(0, 4, 0, nullptr, 0, nullptr);
    gemm_bf<<<dim3(391, 2), 256>>>(0, 4, b1, 2, N_NODES, 128, 256, 1);

    // ---- Layer 2 (gather-first, dim 256; K=256 -> M=512) ----
    gath_n2e_h<<<N_EDGES / 8, 256>>>(2, 5);
    gath_e2n_h<<<N_NODES / 8, 256>>>(0, 5, 0, nullptr, 0, nullptr);
    gemm_bf<<<dim3(391, 4), 256>>>(0, 5, b2, 3, N_NODES, 256, 512, 1);

    // ---- Layer 3 (gemm-first; K=512 -> M=256; epi + pool fused into e2n) ----
    gemm_bf<<<dim3(391, 2), 256>>>(3, 6, nullptr, 0, N_NODES, 512, 256, 0);
    gath_n2e_h<<<N_EDGES / 8, 256>>>(0, 5);
    gath_e2n_h<<<N_NODES / 8, 256>>>(2, 5, 1, b3, 1, batch);

    // ---- MLP head ----
    mlp_k<<<N_GRAPHS, 256>>>(Wl1, bl1, Wl2, bl2, out);
}